// round 13
// baseline (speedup 1.0000x reference)

#include <cuda_runtime.h>
#include <cuda_fp16.h>
#include <math.h>
#include <stdint.h>

// Problem constants
#define BSZ 4
#define SEQ 2048
#define CH  768
#define NH  12
#define HD  64
#define TOK (BSZ*SEQ)   // 8192
#define C3  (3*CH)      // 2304
#define BH  (BSZ*NH)    // 48

// Pre-split hi/lo half storage (allocation-free per harness rules)
__device__ __half g_xnh[TOK*CH],  g_xnl[TOK*CH];     // LN output, x8
__device__ __half g_qh[BH*SEQ*HD], g_ql[BH*SEQ*HD];  // Q, x8
__device__ __half g_kh[BH*SEQ*HD], g_kl[BH*SEQ*HD];  // K, x8
__device__ __half g_vh[BH*SEQ*HD], g_vl[BH*SEQ*HD];  // V, x8
__device__ __half g_atth[TOK*CH], g_attl[TOK*CH];    // attn out, x8
__device__ __half g_wqh[CH*C3],  g_wql[CH*C3];       // w_qkv, x64
__device__ __half g_woh[CH*CH],  g_wol[CH*CH];       // w_out, x64

#define ASCALE 8.0f
#define WSCALE 64.0f
#define CINV   (1.0f/512.0f)
#define SMUL   (0.125f/64.0f)

// ---------------------------------------------------------------------------
// helpers
// ---------------------------------------------------------------------------
__device__ __forceinline__ void splitf(float x, __half& h, __half& l) {
    h = __float2half_rn(x);
    l = __float2half_rn(x - __half2float(h));
}

__device__ __forceinline__ uint32_t split_h2(float a, float b, uint32_t& lo2) {
    __half ha, la, hbb, lb;
    splitf(a, ha, la);
    splitf(b, hbb, lb);
    __half2 hh = __halves2half2(ha, hbb);
    __half2 ll = __halves2half2(la, lb);
    lo2 = *(uint32_t*)&ll;
    return *(uint32_t*)&hh;
}

__device__ __forceinline__ void ldsm4(uint32_t a[4], const void* p) {
    uint32_t addr = (uint32_t)__cvta_generic_to_shared(p);
    asm volatile("ldmatrix.sync.aligned.m8n8.x4.shared.b16 {%0,%1,%2,%3}, [%4];"
                 : "=r"(a[0]), "=r"(a[1]), "=r"(a[2]), "=r"(a[3]) : "r"(addr));
}

__device__ __forceinline__ void ldsm4t(uint32_t a[4], const void* p) {
    uint32_t addr = (uint32_t)__cvta_generic_to_shared(p);
    asm volatile("ldmatrix.sync.aligned.m8n8.x4.trans.shared.b16 {%0,%1,%2,%3}, [%4];"
                 : "=r"(a[0]), "=r"(a[1]), "=r"(a[2]), "=r"(a[3]) : "r"(addr));
}

__device__ __forceinline__ void mma_f16(float c[4], const uint32_t a[4], const uint32_t b[2]) {
    asm volatile(
        "mma.sync.aligned.m16n8k16.row.col.f32.f16.f16.f32 "
        "{%0,%1,%2,%3},{%4,%5,%6,%7},{%8,%9},{%0,%1,%2,%3};"
        : "+f"(c[0]), "+f"(c[1]), "+f"(c[2]), "+f"(c[3])
        : "r"(a[0]), "r"(a[1]), "r"(a[2]), "r"(a[3]), "r"(b[0]), "r"(b[1]));
}

// ---------------------------------------------------------------------------
// 0) Weight split: dst = split(src * 64)
// ---------------------------------------------------------------------------
__global__ void wsplit_kernel(const float* __restrict__ src,
                              __half* __restrict__ dh,
                              __half* __restrict__ dl,
                              int n) {
    int i = blockIdx.x * 256 + threadIdx.x;
    if (i < n) {
        __half h, lo;
        splitf(src[i] * WSCALE, h, lo);
        dh[i] = h; dl[i] = lo;
    }
}

// ---------------------------------------------------------------------------
// 1) LayerNorm: one block per token; writes split halves (x8)
// ---------------------------------------------------------------------------
__global__ void ln_kernel(const float* __restrict__ x,
                          const float* __restrict__ gamma,
                          const float* __restrict__ beta) {
    int t = blockIdx.x;
    const float* xr = x + (size_t)t * CH;
    int i0 = threadIdx.x, i1 = i0 + 256, i2 = i0 + 512;
    float v0 = xr[i0], v1 = xr[i1], v2 = xr[i2];
    float s  = v0 + v1 + v2;
    float s2 = v0*v0 + v1*v1 + v2*v2;
    #pragma unroll
    for (int o = 16; o > 0; o >>= 1) {
        s  += __shfl_down_sync(0xffffffffu, s,  o);
        s2 += __shfl_down_sync(0xffffffffu, s2, o);
    }
    __shared__ float ws[8], ws2[8];
    __shared__ float mu_s, inv_s;
    int w = threadIdx.x >> 5, l = threadIdx.x & 31;
    if (l == 0) { ws[w] = s; ws2[w] = s2; }
    __syncthreads();
    if (threadIdx.x == 0) {
        float a = 0.f, b = 0.f;
        #pragma unroll
        for (int k = 0; k < 8; k++) { a += ws[k]; b += ws2[k]; }
        float mu  = a * (1.0f / CH);
        float var = b * (1.0f / CH) - mu * mu;
        mu_s  = mu;
        inv_s = rsqrtf(var + 1e-5f);
    }
    __syncthreads();
    float mu = mu_s, inv = inv_s;
    size_t base = (size_t)t * CH;
    __half h, lo;
    float o0 = (v0 - mu) * inv * gamma[i0] + beta[i0];
    float o1 = (v1 - mu) * inv * gamma[i1] + beta[i1];
    float o2 = (v2 - mu) * inv * gamma[i2] + beta[i2];
    splitf(o0 * ASCALE, h, lo); g_xnh[base + i0] = h; g_xnl[base + i0] = lo;
    splitf(o1 * ASCALE, h, lo); g_xnh[base + i1] = h; g_xnl[base + i1] = lo;
    splitf(o2 * ASCALE, h, lo); g_xnh[base + i2] = h; g_xnl[base + i2] = lo;
}

// ---------------------------------------------------------------------------
// GEMM config: BM=128, BN=128, BK=16, 128 threads = 4 warps (2x2),
// warp tile 64x64. Double-buffered smem (48KB exactly).
// ---------------------------------------------------------------------------
#define GBM 128
#define GBN 128
#define GBK 16
#define HPAD 24

// 2) QKV GEMM: xn(split) @ wqkv(split) -> q/k/v written as split halves (x8)
__global__ void f16gemm_qkv() {
    __shared__ __half Ah[2][GBM][HPAD], Al[2][GBM][HPAD];
    __shared__ __half Bh[2][GBN][HPAD], Bl[2][GBN][HPAD];

    int tid = threadIdx.x;
    int w = tid >> 5, L = tid & 31;
    int wm = w >> 1, wn = w & 1;
    int m0 = blockIdx.y * GBM;
    int n0 = blockIdx.x * GBN;

    float acc[4][8][4];
    #pragma unroll
    for (int i = 0; i < 4; i++)
        #pragma unroll
        for (int j = 0; j < 8; j++)
            #pragma unroll
            for (int c = 0; c < 4; c++) acc[i][j][c] = 0.f;

    const int KT = CH / GBK;

    // prologue
    {
        #pragma unroll
        for (int i = 0; i < 4; i++) {
            int s = tid + i * 128;
            int r = s >> 2, c = (s & 3) * 4;
            size_t off = (size_t)(m0 + r) * CH + c;
            *(uint2*)&Ah[0][r][c] = *(const uint2*)&g_xnh[off];
            *(uint2*)&Al[0][r][c] = *(const uint2*)&g_xnl[off];
        }
        #pragma unroll
        for (int i = 0; i < 4; i++) {
            int s = tid + i * 128;
            int k = s >> 5, n4 = (s & 31) * 4;
            size_t off = (size_t)k * C3 + n0 + n4;
            uint2 vh = *(const uint2*)&g_wqh[off];
            uint2 vl = *(const uint2*)&g_wql[off];
            const __half* ph = (const __half*)&vh;
            const __half* pl = (const __half*)&vl;
            #pragma unroll
            for (int u = 0; u < 4; u++) {
                Bh[0][n4 + u][k] = ph[u];
                Bl[0][n4 + u][k] = pl[u];
            }
        }
    }
    __syncthreads();

    int a_row_off = ((L >> 3) & 1) * 8 + (L & 7);
    int a_col_off = ((L >> 4) & 1) * 8;
    int b_n_off   = ((L >> 4) & 1) * 8 + (L & 7);
    int b_k_off   = ((L >> 3) & 1) * 8;

    for (int kt = 0; kt < KT; kt++) {
        int cur = kt & 1, nxt = cur ^ 1;
        uint2 pah[4], pal[4], pbh[4], pbl[4];
        bool has_next = (kt + 1 < KT);
        if (has_next) {
            int kbase = (kt + 1) * GBK;
            #pragma unroll
            for (int i = 0; i < 4; i++) {
                int s = tid + i * 128;
                int r = s >> 2, c = (s & 3) * 4;
                size_t off = (size_t)(m0 + r) * CH + kbase + c;
                pah[i] = *(const uint2*)&g_xnh[off];
                pal[i] = *(const uint2*)&g_xnl[off];
            }
            #pragma unroll
            for (int i = 0; i < 4; i++) {
                int s = tid + i * 128;
                int k = s >> 5, n4 = (s & 31) * 4;
                size_t off = (size_t)(kbase + k) * C3 + n0 + n4;
                pbh[i] = *(const uint2*)&g_wqh[off];
                pbl[i] = *(const uint2*)&g_wql[off];
            }
        }
        // compute
        {
            uint32_t afh[4][4], afl[4][4];
            #pragma unroll
            for (int mf = 0; mf < 4; mf++) {
                int row = wm * 64 + mf * 16 + a_row_off;
                ldsm4(afh[mf], &Ah[cur][row][a_col_off]);
                ldsm4(afl[mf], &Al[cur][row][a_col_off]);
            }
            #pragma unroll
            for (int p = 0; p < 4; p++) {
                int n = wn * 64 + p * 16 + b_n_off;
                uint32_t th[4], tl[4];
                ldsm4(th, &Bh[cur][n][b_k_off]);
                ldsm4(tl, &Bl[cur][n][b_k_off]);
                #pragma unroll
                for (int q = 0; q < 2; q++) {
                    int nf = 2 * p + q;
                    const uint32_t bh2[2] = {th[2*q], th[2*q+1]};
                    const uint32_t bl2[2] = {tl[2*q], tl[2*q+1]};
                    #pragma unroll
                    for (int mf = 0; mf < 4; mf++) {
                        mma_f16(acc[mf][nf], afh[mf], bh2);
                        mma_f16(acc[mf][nf], afh[mf], bl2);
                        mma_f16(acc[mf][nf], afl[mf], bh2);
                    }
                }
            }
        }
        if (has_next) {
            #pragma unroll
            for (int i = 0; i < 4; i++) {
                int s = tid + i * 128;
                int r = s >> 2, c = (s & 3) * 4;
                *(uint2*)&Ah[nxt][r][c] = pah[i];
                *(uint2*)&Al[nxt][r][c] = pal[i];
            }
            #pragma unroll
            for (int i = 0; i < 4; i++) {
                int s = tid + i * 128;
                int k = s >> 5, n4 = (s & 31) * 4;
                const __half* ph = (const __half*)&pbh[i];
                const __half* pl = (const __half*)&pbl[i];
                #pragma unroll
                for (int u = 0; u < 4; u++) {
                    Bh[nxt][n4 + u][k] = ph[u];
                    Bl[nxt][n4 + u][k] = pl[u];
                }
            }
        }
        __syncthreads();
    }

    // epilogue: val = acc/512; store split(val*8) = split(acc/64)
    int g = L >> 2, t2 = (L & 3) * 2;
    int hb = n0 + wn * 64;            // 64-aligned: one head, one of q/k/v
    int which = hb / CH;
    int h = (hb % CH) >> 6;
    __half* dsth = (which == 0) ? g_qh : ((which == 1) ? g_kh : g_vh);
    __half* dstl = (which == 0) ? g_ql : ((which == 1) ? g_kl : g_vl);
    #pragma unroll
    for (int mf = 0; mf < 4; mf++)
        #pragma unroll
        for (int nf = 0; nf < 8; nf++) {
            int d = nf * 8 + t2;
            #pragma unroll
            for (int half = 0; half < 2; half++) {
                int m = m0 + wm * 64 + mf * 16 + g + half * 8;
                int b = m >> 11, n = m & (SEQ - 1);
                size_t off = ((size_t)(b * NH + h) * SEQ + n) * HD + d;
                uint32_t lo2;
                uint32_t hi2 = split_h2(acc[mf][nf][half*2]   * (1.0f/64.0f),
                                        acc[mf][nf][half*2+1] * (1.0f/64.0f), lo2);
                *(uint32_t*)&dsth[off] = hi2;
                *(uint32_t*)&dstl[off] = lo2;
            }
        }
}

// 4) Output GEMM: att(split) @ w_out(split) + bias + residual -> fp32 out
__global__ void f16gemm_out(const float* __restrict__ bias,
                            const float* __restrict__ resid,
                            float* __restrict__ outp) {
    __shared__ __half Ah[2][GBM][HPAD], Al[2][GBM][HPAD];
    __shared__ __half Bh[2][GBN][HPAD], Bl[2][GBN][HPAD];

    int tid = threadIdx.x;
    int w = tid >> 5, L = tid & 31;
    int wm = w >> 1, wn = w & 1;
    int m0 = blockIdx.y * GBM;
    int n0 = blockIdx.x * GBN;

    float acc[4][8][4];
    #pragma unroll
    for (int i = 0; i < 4; i++)
        #pragma unroll
        for (int j = 0; j < 8; j++)
            #pragma unroll
            for (int c = 0; c < 4; c++) acc[i][j][c] = 0.f;

    const int KT = CH / GBK;

    {
        #pragma unroll
        for (int i = 0; i < 4; i++) {
            int s = tid + i * 128;
            int r = s >> 2, c = (s & 3) * 4;
            size_t off = (size_t)(m0 + r) * CH + c;
            *(uint2*)&Ah[0][r][c] = *(const uint2*)&g_atth[off];
            *(uint2*)&Al[0][r][c] = *(const uint2*)&g_attl[off];
        }
        #pragma unroll
        for (int i = 0; i < 4; i++) {
            int s = tid + i * 128;
            int k = s >> 5, n4 = (s & 31) * 4;
            size_t off = (size_t)k * CH + n0 + n4;
            uint2 vh = *(const uint2*)&g_woh[off];
            uint2 vl = *(const uint2*)&g_wol[off];
            const __half* ph = (const __half*)&vh;
            const __half* pl = (const __half*)&vl;
            #pragma unroll
            for (int u = 0; u < 4; u++) {
                Bh[0][n4 + u][k] = ph[u];
                Bl[0][n4 + u][k] = pl[u];
            }
        }
    }
    __syncthreads();

    int a_row_off = ((L >> 3) & 1) * 8 + (L & 7);
    int a_col_off = ((L >> 4) & 1) * 8;
    int b_n_off   = ((L >> 4) & 1) * 8 + (L & 7);
    int b_k_off   = ((L >> 3) & 1) * 8;

    for (int kt = 0; kt < KT; kt++) {
        int cur = kt & 1, nxt = cur ^ 1;
        uint2 pah[4], pal[4], pbh[4], pbl[4];
        bool has_next = (kt + 1 < KT);
        if (has_next) {
            int kbase = (kt + 1) * GBK;
            #pragma unroll
            for (int i = 0; i < 4; i++) {
                int s = tid + i * 128;
                int r = s >> 2, c = (s & 3) * 4;
                size_t off = (size_t)(m0 + r) * CH + kbase + c;
                pah[i] = *(const uint2*)&g_atth[off];
                pal[i] = *(const uint2*)&g_attl[off];
            }
            #pragma unroll
            for (int i = 0; i < 4; i++) {
                int s = tid + i * 128;
                int k = s >> 5, n4 = (s & 31) * 4;
                size_t off = (size_t)(kbase + k) * CH + n0 + n4;
                pbh[i] = *(const uint2*)&g_woh[off];
                pbl[i] = *(const uint2*)&g_wol[off];
            }
        }
        {
            uint32_t afh[4][4], afl[4][4];
            #pragma unroll
            for (int mf = 0; mf < 4; mf++) {
                int row = wm * 64 + mf * 16 + a_row_off;
                ldsm4(afh[mf], &Ah[cur][row][a_col_off]);
                ldsm4(afl[mf], &Al[cur][row][a_col_off]);
            }
            #pragma unroll
            for (int p = 0; p < 4; p++) {
                int n = wn * 64 + p * 16 + b_n_off;
                uint32_t th[4], tl[4];
                ldsm4(th, &Bh[cur][n][b_k_off]);
                ldsm4(tl, &Bl[cur][n][b_k_off]);
                #pragma unroll
                for (int q = 0; q < 2; q++) {
                    int nf = 2 * p + q;
                    const uint32_t bh2[2] = {th[2*q], th[2*q+1]};
                    const uint32_t bl2[2] = {tl[2*q], tl[2*q+1]};
                    #pragma unroll
                    for (int mf = 0; mf < 4; mf++) {
                        mma_f16(acc[mf][nf], afh[mf], bh2);
                        mma_f16(acc[mf][nf], afh[mf], bl2);
                        mma_f16(acc[mf][nf], afl[mf], bh2);
                    }
                }
            }
        }
        if (has_next) {
            #pragma unroll
            for (int i = 0; i < 4; i++) {
                int s = tid + i * 128;
                int r = s >> 2, c = (s & 3) * 4;
                *(uint2*)&Ah[nxt][r][c] = pah[i];
                *(uint2*)&Al[nxt][r][c] = pal[i];
            }
            #pragma unroll
            for (int i = 0; i < 4; i++) {
                int s = tid + i * 128;
                int k = s >> 5, n4 = (s & 31) * 4;
                const __half* ph = (const __half*)&pbh[i];
                const __half* pl = (const __half*)&pbl[i];
                #pragma unroll
                for (int u = 0; u < 4; u++) {
                    Bh[nxt][n4 + u][k] = ph[u];
                    Bl[nxt][n4 + u][k] = pl[u];
                }
            }
        }
        __syncthreads();
    }

    int g = L >> 2, t2 = (L & 3) * 2;
    #pragma unroll
    for (int mf = 0; mf < 4; mf++)
        #pragma unroll
        for (int nf = 0; nf < 8; nf++) {
            int col = n0 + wn * 64 + nf * 8 + t2;
            float2 bv = *(const float2*)&bias[col];
            #pragma unroll
            for (int half = 0; half < 2; half++) {
                int m = m0 + wm * 64 + mf * 16 + g + half * 8;
                float2 rv = *(const float2*)&resid[(size_t)m * CH + col];
                float2 v = make_float2(acc[mf][nf][half*2]   * CINV + bv.x + rv.x,
                                       acc[mf][nf][half*2+1] * CINV + bv.y + rv.y);
                *(float2*)&outp[(size_t)m * CH + col] = v;
            }
        }
}

// ---------------------------------------------------------------------------
// 3) Flash attention, fp16x3, pre-split Q/K/V. P kept in registers
//    (C-fragment == A-fragment layout): no smem round-trip, no P ldsm.
// ---------------------------------------------------------------------------
#define APAD 72

__global__ void f16attn() {
    __shared__ __half Kh[64][APAD], Kl[64][APAD];
    __shared__ __half Vh[64][APAD], Vl[64][APAD];

    int tid = threadIdx.x;
    int w = tid >> 5, L = tid & 31;
    int bh = blockIdx.y;
    int q0 = blockIdx.x * 64;

    size_t hbase = (size_t)bh * SEQ * HD;

    int a_row_off = ((L >> 3) & 1) * 8 + (L & 7);
    int a_col_off = ((L >> 4) & 1) * 8;
    int b_n_off   = ((L >> 4) & 1) * 8 + (L & 7);
    int b_k_off   = ((L >> 3) & 1) * 8;
    int g = L >> 2, t2 = (L & 3) * 2;

    // Stage pre-split Q through Kh/Kl, build persistent fragments
    #pragma unroll
    for (int i = 0; i < 8; i++) {
        int s = tid + i * 128;
        int r = s >> 4, d4 = (s & 15) * 4;
        size_t off = hbase + (size_t)(q0 + r) * HD + d4;
        *(uint2*)&Kh[r][d4] = *(const uint2*)&g_qh[off];
        *(uint2*)&Kl[r][d4] = *(const uint2*)&g_ql[off];
    }
    __syncthreads();
    uint32_t qfh[4][4], qfl[4][4];
    #pragma unroll
    for (int ks = 0; ks < 4; ks++) {
        int row = w * 16 + a_row_off;
        ldsm4(qfh[ks], &Kh[row][ks * 16 + a_col_off]);
        ldsm4(qfl[ks], &Kl[row][ks * 16 + a_col_off]);
    }

    float m0r = -1e30f, m1r = -1e30f, l0 = 0.f, l1 = 0.f;
    float oacc[8][4];
    #pragma unroll
    for (int j = 0; j < 8; j++)
        #pragma unroll
        for (int c = 0; c < 4; c++) oacc[j][c] = 0.f;

    for (int s0 = 0; s0 < SEQ; s0 += 64) {
        __syncthreads();   // previous K/V fully consumed
        #pragma unroll
        for (int i = 0; i < 8; i++) {
            int s = tid + i * 128;
            int kv = s >> 4, d4 = (s & 15) * 4;
            size_t off = hbase + (size_t)(s0 + kv) * HD + d4;
            *(uint2*)&Kh[kv][d4] = *(const uint2*)&g_kh[off];
            *(uint2*)&Kl[kv][d4] = *(const uint2*)&g_kl[off];
            *(uint2*)&Vh[kv][d4] = *(const uint2*)&g_vh[off];
            *(uint2*)&Vl[kv][d4] = *(const uint2*)&g_vl[off];
        }
        __syncthreads();

        // S = (8Q)(8K)^T ; rescale by 0.125/64 after
        float sacc[8][4];
        #pragma unroll
        for (int j = 0; j < 8; j++)
            #pragma unroll
            for (int c = 0; c < 4; c++) sacc[j][c] = 0.f;
        #pragma unroll
        for (int ks = 0; ks < 4; ks++) {
            #pragma unroll
            for (int p = 0; p < 4; p++) {
                int n = p * 16 + b_n_off;
                uint32_t th[4], tl[4];
                ldsm4(th, &Kh[n][ks * 16 + b_k_off]);
                ldsm4(tl, &Kl[n][ks * 16 + b_k_off]);
                #pragma unroll
                for (int q = 0; q < 2; q++) {
                    int j = 2 * p + q;
                    const uint32_t bh2[2] = {th[2*q], th[2*q+1]};
                    const uint32_t bl2[2] = {tl[2*q], tl[2*q+1]};
                    mma_f16(sacc[j], qfh[ks], bh2);
                    mma_f16(sacc[j], qfh[ks], bl2);
                    mma_f16(sacc[j], qfl[ks], bh2);
                }
            }
        }
        #pragma unroll
        for (int j = 0; j < 8; j++)
            #pragma unroll
            for (int c = 0; c < 4; c++) sacc[j][c] *= SMUL;

        // Online softmax on fragments (rows g and g+8 of this warp's 16)
        float mx0 = -1e30f, mx1 = -1e30f;
        #pragma unroll
        for (int j = 0; j < 8; j++) {
            mx0 = fmaxf(mx0, fmaxf(sacc[j][0], sacc[j][1]));
            mx1 = fmaxf(mx1, fmaxf(sacc[j][2], sacc[j][3]));
        }
        #pragma unroll
        for (int o = 1; o <= 2; o <<= 1) {
            mx0 = fmaxf(mx0, __shfl_xor_sync(0xffffffffu, mx0, o));
            mx1 = fmaxf(mx1, __shfl_xor_sync(0xffffffffu, mx1, o));
        }
        float mn0 = fmaxf(m0r, mx0), mn1 = fmaxf(m1r, mx1);
        float f0 = __expf(m0r - mn0), f1 = __expf(m1r - mn1);
        m0r = mn0; m1r = mn1;
        float rs0 = 0.f, rs1 = 0.f;
        #pragma unroll
        for (int j = 0; j < 8; j++) {
            sacc[j][0] = __expf(sacc[j][0] - mn0);
            sacc[j][1] = __expf(sacc[j][1] - mn0);
            sacc[j][2] = __expf(sacc[j][2] - mn1);
            sacc[j][3] = __expf(sacc[j][3] - mn1);
            rs0 += sacc[j][0] + sacc[j][1];
            rs1 += sacc[j][2] + sacc[j][3];
        }
        #pragma unroll
        for (int o = 1; o <= 2; o <<= 1) {
            rs0 += __shfl_xor_sync(0xffffffffu, rs0, o);
            rs1 += __shfl_xor_sync(0xffffffffu, rs1, o);
        }
        l0 = l0 * f0 + rs0;
        l1 = l1 * f1 + rs1;
        #pragma unroll
        for (int j = 0; j < 8; j++) {
            oacc[j][0] *= f0; oacc[j][1] *= f0;
            oacc[j][2] *= f1; oacc[j][3] *= f1;
        }

        // Build P A-fragments in registers: x64 scaling, hi/lo split.
        // A-frag for k-chunk ks: {h2(j0:c0,c1), h2(j0:c2,c3), h2(j1:c0,c1), h2(j1:c2,c3)}
        // where j0=2ks (k 0..7), j1=2ks+1 (k 8..15).
        uint32_t pfh[4][4], pfl[4][4];
        #pragma unroll
        for (int ks = 0; ks < 4; ks++) {
            int j0 = 2 * ks, j1 = 2 * ks + 1;
            pfh[ks][0] = split_h2(sacc[j0][0] * 64.0f, sacc[j0][1] * 64.0f, pfl[ks][0]);
            pfh[ks][1] = split_h2(sacc[j0][2] * 64.0f, sacc[j0][3] * 64.0f, pfl[ks][1]);
            pfh[ks][2] = split_h2(sacc[j1][0] * 64.0f, sacc[j1][1] * 64.0f, pfl[ks][2]);
            pfh[ks][3] = split_h2(sacc[j1][2] * 64.0f, sacc[j1][3] * 64.0f, pfl[ks][3]);
        }

        // O += (64P)(8V)   (V via ldmatrix.trans; P from registers)
        #pragma unroll
        for (int ks = 0; ks < 4; ks++) {
            #pragma unroll
            for (int p = 0; p < 4; p++) {
                uint32_t th[4], tl[4];
                ldsm4t(th, &Vh[ks * 16 + a_row_off][p * 16 + a_col_off]);
                ldsm4t(tl, &Vl[ks * 16 + a_row_off][p * 16 + a_col_off]);
                #pragma unroll
                for (int q = 0; q < 2; q++) {
                    int j = 2 * p + q;
                    const uint32_t bh2[2] = {th[2*q], th[2*q+1]};
                    const uint32_t bl2[2] = {tl[2*q], tl[2*q+1]};
                    mma_f16(oacc[j], pfh[ks], bh2);
                    mma_f16(oacc[j], pfh[ks], bl2);
                    mma_f16(oacc[j], pfl[ks], bh2);
                }
            }
        }
    }

    // Epilogue: o_actual = oacc/(512 l); store split(o_actual*8) = split(oacc/(64 l))
    int b = bh / NH, h = bh % NH;
    float inv0 = (1.0f / 64.0f) / l0, inv1 = (1.0f / 64.0f) / l1;
    #pragma unroll
    for (int j = 0; j < 8; j++) {
        int d = j * 8 + t2;
        int q = q0 + w * 16 + g;
        size_t off0 = ((size_t)(b * SEQ + q)) * CH + h * HD + d;
        size_t off1 = ((size_t)(b * SEQ + q + 8)) * CH + h * HD + d;
        uint32_t lo2;
        uint32_t hi2 = split_h2(oacc[j][0] * inv0, oacc[j][1] * inv0, lo2);
        *(uint32_t*)&g_atth[off0] = hi2;
        *(uint32_t*)&g_attl[off0] = lo2;
        hi2 = split_h2(oacc[j][2] * inv1, oacc[j][3] * inv1, lo2);
        *(uint32_t*)&g_atth[off1] = hi2;
        *(uint32_t*)&g_attl[off1] = lo2;
    }
}

// ---------------------------------------------------------------------------
extern "C" void kernel_launch(void* const* d_in, const int* in_sizes, int n_in,
                              void* d_out, int out_size) {
    const float* img   = (const float*)d_in[0];
    const float* gamma = (const float*)d_in[1];
    const float* beta  = (const float*)d_in[2];
    const float* w_qkv = (const float*)d_in[3];
    const float* w_out = (const float*)d_in[4];
    const float* b_out = (const float*)d_in[5];
    float* out = (float*)d_out;

    __half *wqh, *wql, *woh, *wol;
    cudaGetSymbolAddress((void**)&wqh, g_wqh);
    cudaGetSymbolAddress((void**)&wql, g_wql);
    cudaGetSymbolAddress((void**)&woh, g_woh);
    cudaGetSymbolAddress((void**)&wol, g_wol);

    wsplit_kernel<<<(CH * C3 + 255) / 256, 256>>>(w_qkv, wqh, wql, CH * C3);
    wsplit_kernel<<<(CH * CH + 255) / 256, 256>>>(w_out, woh, wol, CH * CH);
    ln_kernel<<<TOK, 256>>>(img, gamma, beta);
    f16gemm_qkv<<<dim3(C3 / GBN, TOK / GBM), 128>>>();
    f16attn<<<dim3(SEQ / 64, BH), 128>>>();
    f16gemm_out<<<dim3(CH / GBN, TOK / GBM), 128>>>(b_out, img, out);
}

// round 14
// speedup vs baseline: 1.2433x; 1.2433x over previous

#include <cuda_runtime.h>
#include <cuda_fp16.h>
#include <math.h>
#include <stdint.h>

// Problem constants
#define BSZ 4
#define SEQ 2048
#define CH  768
#define NH  12
#define HD  64
#define TOK (BSZ*SEQ)   // 8192
#define C3  (3*CH)      // 2304
#define BH  (BSZ*NH)    // 48

// Pre-split hi/lo half storage (allocation-free per harness rules)
__device__ __half g_xnh[TOK*CH],  g_xnl[TOK*CH];     // LN output, x8
__device__ __half g_qh[BH*SEQ*HD], g_ql[BH*SEQ*HD];  // Q, x8
__device__ __half g_kh[BH*SEQ*HD], g_kl[BH*SEQ*HD];  // K, x8
__device__ __half g_vh[BH*SEQ*HD], g_vl[BH*SEQ*HD];  // V, x8
__device__ __half g_atth[TOK*CH], g_attl[TOK*CH];    // attn out, x8
__device__ __half g_wqh[CH*C3],  g_wql[CH*C3];       // w_qkv, x64
__device__ __half g_woh[CH*CH],  g_wol[CH*CH];       // w_out, x64

#define ASCALE 8.0f
#define WSCALE 64.0f
#define CINV   (1.0f/512.0f)
#define SMUL   (0.125f/64.0f)

// ---------------------------------------------------------------------------
// helpers
// ---------------------------------------------------------------------------
__device__ __forceinline__ void splitf(float x, __half& h, __half& l) {
    h = __float2half_rn(x);
    l = __float2half_rn(x - __half2float(h));
}

__device__ __forceinline__ uint32_t split_h2(float a, float b, uint32_t& lo2) {
    __half ha, la, hbb, lb;
    splitf(a, ha, la);
    splitf(b, hbb, lb);
    __half2 hh = __halves2half2(ha, hbb);
    __half2 ll = __halves2half2(la, lb);
    lo2 = *(uint32_t*)&ll;
    return *(uint32_t*)&hh;
}

__device__ __forceinline__ void ldsm4(uint32_t a[4], const void* p) {
    uint32_t addr = (uint32_t)__cvta_generic_to_shared(p);
    asm volatile("ldmatrix.sync.aligned.m8n8.x4.shared.b16 {%0,%1,%2,%3}, [%4];"
                 : "=r"(a[0]), "=r"(a[1]), "=r"(a[2]), "=r"(a[3]) : "r"(addr));
}

__device__ __forceinline__ void ldsm4t(uint32_t a[4], const void* p) {
    uint32_t addr = (uint32_t)__cvta_generic_to_shared(p);
    asm volatile("ldmatrix.sync.aligned.m8n8.x4.trans.shared.b16 {%0,%1,%2,%3}, [%4];"
                 : "=r"(a[0]), "=r"(a[1]), "=r"(a[2]), "=r"(a[3]) : "r"(addr));
}

__device__ __forceinline__ void mma_f16(float c[4], const uint32_t a[4], const uint32_t b[2]) {
    asm volatile(
        "mma.sync.aligned.m16n8k16.row.col.f32.f16.f16.f32 "
        "{%0,%1,%2,%3},{%4,%5,%6,%7},{%8,%9},{%0,%1,%2,%3};"
        : "+f"(c[0]), "+f"(c[1]), "+f"(c[2]), "+f"(c[3])
        : "r"(a[0]), "r"(a[1]), "r"(a[2]), "r"(a[3]), "r"(b[0]), "r"(b[1]));
}

// ---------------------------------------------------------------------------
// 0) Weight split: dst = split(src * 64)
// ---------------------------------------------------------------------------
__global__ void wsplit_kernel(const float* __restrict__ src,
                              __half* __restrict__ dh,
                              __half* __restrict__ dl,
                              int n) {
    int i = blockIdx.x * 256 + threadIdx.x;
    if (i < n) {
        __half h, lo;
        splitf(src[i] * WSCALE, h, lo);
        dh[i] = h; dl[i] = lo;
    }
}

// ---------------------------------------------------------------------------
// 1) LayerNorm: one block per token; writes split halves (x8)
// ---------------------------------------------------------------------------
__global__ void ln_kernel(const float* __restrict__ x,
                          const float* __restrict__ gamma,
                          const float* __restrict__ beta) {
    int t = blockIdx.x;
    const float* xr = x + (size_t)t * CH;
    int i0 = threadIdx.x, i1 = i0 + 256, i2 = i0 + 512;
    float v0 = xr[i0], v1 = xr[i1], v2 = xr[i2];
    float s  = v0 + v1 + v2;
    float s2 = v0*v0 + v1*v1 + v2*v2;
    #pragma unroll
    for (int o = 16; o > 0; o >>= 1) {
        s  += __shfl_down_sync(0xffffffffu, s,  o);
        s2 += __shfl_down_sync(0xffffffffu, s2, o);
    }
    __shared__ float ws[8], ws2[8];
    __shared__ float mu_s, inv_s;
    int w = threadIdx.x >> 5, l = threadIdx.x & 31;
    if (l == 0) { ws[w] = s; ws2[w] = s2; }
    __syncthreads();
    if (threadIdx.x == 0) {
        float a = 0.f, b = 0.f;
        #pragma unroll
        for (int k = 0; k < 8; k++) { a += ws[k]; b += ws2[k]; }
        float mu  = a * (1.0f / CH);
        float var = b * (1.0f / CH) - mu * mu;
        mu_s  = mu;
        inv_s = rsqrtf(var + 1e-5f);
    }
    __syncthreads();
    float mu = mu_s, inv = inv_s;
    size_t base = (size_t)t * CH;
    __half h, lo;
    float o0 = (v0 - mu) * inv * gamma[i0] + beta[i0];
    float o1 = (v1 - mu) * inv * gamma[i1] + beta[i1];
    float o2 = (v2 - mu) * inv * gamma[i2] + beta[i2];
    splitf(o0 * ASCALE, h, lo); g_xnh[base + i0] = h; g_xnl[base + i0] = lo;
    splitf(o1 * ASCALE, h, lo); g_xnh[base + i1] = h; g_xnl[base + i1] = lo;
    splitf(o2 * ASCALE, h, lo); g_xnh[base + i2] = h; g_xnl[base + i2] = lo;
}

// ---------------------------------------------------------------------------
// GEMM config (r12 proven): BM=128, BN=64, BK=16, 128 threads = 4 warps (2x2),
// warp tile 64x32. Double-buffered smem. Operands pre-split.
// ---------------------------------------------------------------------------
#define GBM 128
#define GBN 64
#define GBK 16
#define HPAD 24

// 2) QKV GEMM: xn(split) @ wqkv(split) -> q/k/v written as split halves (x8)
__global__ void f16gemm_qkv() {
    __shared__ __half Ah[2][GBM][HPAD], Al[2][GBM][HPAD];
    __shared__ __half Bh[2][GBN][HPAD], Bl[2][GBN][HPAD];

    int tid = threadIdx.x;
    int w = tid >> 5, L = tid & 31;
    int wm = w >> 1, wn = w & 1;
    int m0 = blockIdx.y * GBM;
    int n0 = blockIdx.x * GBN;

    float acc[4][4][4];
    #pragma unroll
    for (int i = 0; i < 4; i++)
        #pragma unroll
        for (int j = 0; j < 4; j++)
            #pragma unroll
            for (int c = 0; c < 4; c++) acc[i][j][c] = 0.f;

    int b_n  = tid & 63;
    int b_k0 = (tid >> 6) * 8;
    const int KT = CH / GBK;

    {
        #pragma unroll
        for (int i = 0; i < 4; i++) {
            int s = tid + i * 128;
            int r = s >> 2, c = (s & 3) * 4;
            size_t off = (size_t)(m0 + r) * CH + c;
            *(uint2*)&Ah[0][r][c] = *(const uint2*)&g_xnh[off];
            *(uint2*)&Al[0][r][c] = *(const uint2*)&g_xnl[off];
        }
        #pragma unroll
        for (int j = 0; j < 8; j++) {
            size_t off = (size_t)(b_k0 + j) * C3 + n0 + b_n;
            Bh[0][b_n][b_k0 + j] = g_wqh[off];
            Bl[0][b_n][b_k0 + j] = g_wql[off];
        }
    }
    __syncthreads();

    int a_row_off = ((L >> 3) & 1) * 8 + (L & 7);
    int a_col_off = ((L >> 4) & 1) * 8;
    int b_n_off   = ((L >> 4) & 1) * 8 + (L & 7);
    int b_k_off   = ((L >> 3) & 1) * 8;

    for (int kt = 0; kt < KT; kt++) {
        int cur = kt & 1, nxt = cur ^ 1;
        uint2 pah[4], pal[4];
        __half pbh[8], pbl[8];
        bool has_next = (kt + 1 < KT);
        if (has_next) {
            int kbase = (kt + 1) * GBK;
            #pragma unroll
            for (int i = 0; i < 4; i++) {
                int s = tid + i * 128;
                int r = s >> 2, c = (s & 3) * 4;
                size_t off = (size_t)(m0 + r) * CH + kbase + c;
                pah[i] = *(const uint2*)&g_xnh[off];
                pal[i] = *(const uint2*)&g_xnl[off];
            }
            #pragma unroll
            for (int j = 0; j < 8; j++) {
                size_t off = (size_t)(kbase + b_k0 + j) * C3 + n0 + b_n;
                pbh[j] = g_wqh[off];
                pbl[j] = g_wql[off];
            }
        }
        {
            uint32_t afh[4][4], afl[4][4];
            #pragma unroll
            for (int mf = 0; mf < 4; mf++) {
                int row = wm * 64 + mf * 16 + a_row_off;
                ldsm4(afh[mf], &Ah[cur][row][a_col_off]);
                ldsm4(afl[mf], &Al[cur][row][a_col_off]);
            }
            #pragma unroll
            for (int p = 0; p < 2; p++) {
                int n = wn * 32 + p * 16 + b_n_off;
                uint32_t th[4], tl[4];
                ldsm4(th, &Bh[cur][n][b_k_off]);
                ldsm4(tl, &Bl[cur][n][b_k_off]);
                #pragma unroll
                for (int q = 0; q < 2; q++) {
                    int nf = 2 * p + q;
                    const uint32_t bh2[2] = {th[2*q], th[2*q+1]};
                    const uint32_t bl2[2] = {tl[2*q], tl[2*q+1]};
                    #pragma unroll
                    for (int mf = 0; mf < 4; mf++) {
                        mma_f16(acc[mf][nf], afh[mf], bh2);
                        mma_f16(acc[mf][nf], afh[mf], bl2);
                        mma_f16(acc[mf][nf], afl[mf], bh2);
                    }
                }
            }
        }
        if (has_next) {
            #pragma unroll
            for (int i = 0; i < 4; i++) {
                int s = tid + i * 128;
                int r = s >> 2, c = (s & 3) * 4;
                *(uint2*)&Ah[nxt][r][c] = pah[i];
                *(uint2*)&Al[nxt][r][c] = pal[i];
            }
            #pragma unroll
            for (int j = 0; j < 8; j++) {
                Bh[nxt][b_n][b_k0 + j] = pbh[j];
                Bl[nxt][b_n][b_k0 + j] = pbl[j];
            }
        }
        __syncthreads();
    }

    // epilogue: val = acc/512; store split(val*8) = split(acc/64)
    int g = L >> 2, t2 = (L & 3) * 2;
    int which = n0 / CH;
    int h = (n0 % CH) >> 6;
    __half* dsth = (which == 0) ? g_qh : ((which == 1) ? g_kh : g_vh);
    __half* dstl = (which == 0) ? g_ql : ((which == 1) ? g_kl : g_vl);
    #pragma unroll
    for (int mf = 0; mf < 4; mf++)
        #pragma unroll
        for (int nf = 0; nf < 4; nf++) {
            int d = wn * 32 + nf * 8 + t2;
            #pragma unroll
            for (int half = 0; half < 2; half++) {
                int m = m0 + wm * 64 + mf * 16 + g + half * 8;
                int b = m >> 11, n = m & (SEQ - 1);
                size_t off = ((size_t)(b * NH + h) * SEQ + n) * HD + d;
                uint32_t lo2;
                uint32_t hi2 = split_h2(acc[mf][nf][half*2]   * (1.0f/64.0f),
                                        acc[mf][nf][half*2+1] * (1.0f/64.0f), lo2);
                *(uint32_t*)&dsth[off] = hi2;
                *(uint32_t*)&dstl[off] = lo2;
            }
        }
}

// 4) Output GEMM: att(split) @ w_out(split) + bias + residual -> fp32 out
__global__ void f16gemm_out(const float* __restrict__ bias,
                            const float* __restrict__ resid,
                            float* __restrict__ outp) {
    __shared__ __half Ah[2][GBM][HPAD], Al[2][GBM][HPAD];
    __shared__ __half Bh[2][GBN][HPAD], Bl[2][GBN][HPAD];

    int tid = threadIdx.x;
    int w = tid >> 5, L = tid & 31;
    int wm = w >> 1, wn = w & 1;
    int m0 = blockIdx.y * GBM;
    int n0 = blockIdx.x * GBN;

    float acc[4][4][4];
    #pragma unroll
    for (int i = 0; i < 4; i++)
        #pragma unroll
        for (int j = 0; j < 4; j++)
            #pragma unroll
            for (int c = 0; c < 4; c++) acc[i][j][c] = 0.f;

    int b_n  = tid & 63;
    int b_k0 = (tid >> 6) * 8;
    const int KT = CH / GBK;

    {
        #pragma unroll
        for (int i = 0; i < 4; i++) {
            int s = tid + i * 128;
            int r = s >> 2, c = (s & 3) * 4;
            size_t off = (size_t)(m0 + r) * CH + c;
            *(uint2*)&Ah[0][r][c] = *(const uint2*)&g_atth[off];
            *(uint2*)&Al[0][r][c] = *(const uint2*)&g_attl[off];
        }
        #pragma unroll
        for (int j = 0; j < 8; j++) {
            size_t off = (size_t)(b_k0 + j) * CH + n0 + b_n;
            Bh[0][b_n][b_k0 + j] = g_woh[off];
            Bl[0][b_n][b_k0 + j] = g_wol[off];
        }
    }
    __syncthreads();

    int a_row_off = ((L >> 3) & 1) * 8 + (L & 7);
    int a_col_off = ((L >> 4) & 1) * 8;
    int b_n_off   = ((L >> 4) & 1) * 8 + (L & 7);
    int b_k_off   = ((L >> 3) & 1) * 8;

    for (int kt = 0; kt < KT; kt++) {
        int cur = kt & 1, nxt = cur ^ 1;
        uint2 pah[4], pal[4];
        __half pbh[8], pbl[8];
        bool has_next = (kt + 1 < KT);
        if (has_next) {
            int kbase = (kt + 1) * GBK;
            #pragma unroll
            for (int i = 0; i < 4; i++) {
                int s = tid + i * 128;
                int r = s >> 2, c = (s & 3) * 4;
                size_t off = (size_t)(m0 + r) * CH + kbase + c;
                pah[i] = *(const uint2*)&g_atth[off];
                pal[i] = *(const uint2*)&g_attl[off];
            }
            #pragma unroll
            for (int j = 0; j < 8; j++) {
                size_t off = (size_t)(kbase + b_k0 + j) * CH + n0 + b_n;
                pbh[j] = g_woh[off];
                pbl[j] = g_wol[off];
            }
        }
        {
            uint32_t afh[4][4], afl[4][4];
            #pragma unroll
            for (int mf = 0; mf < 4; mf++) {
                int row = wm * 64 + mf * 16 + a_row_off;
                ldsm4(afh[mf], &Ah[cur][row][a_col_off]);
                ldsm4(afl[mf], &Al[cur][row][a_col_off]);
            }
            #pragma unroll
            for (int p = 0; p < 2; p++) {
                int n = wn * 32 + p * 16 + b_n_off;
                uint32_t th[4], tl[4];
                ldsm4(th, &Bh[cur][n][b_k_off]);
                ldsm4(tl, &Bl[cur][n][b_k_off]);
                #pragma unroll
                for (int q = 0; q < 2; q++) {
                    int nf = 2 * p + q;
                    const uint32_t bh2[2] = {th[2*q], th[2*q+1]};
                    const uint32_t bl2[2] = {tl[2*q], tl[2*q+1]};
                    #pragma unroll
                    for (int mf = 0; mf < 4; mf++) {
                        mma_f16(acc[mf][nf], afh[mf], bh2);
                        mma_f16(acc[mf][nf], afh[mf], bl2);
                        mma_f16(acc[mf][nf], afl[mf], bh2);
                    }
                }
            }
        }
        if (has_next) {
            #pragma unroll
            for (int i = 0; i < 4; i++) {
                int s = tid + i * 128;
                int r = s >> 2, c = (s & 3) * 4;
                *(uint2*)&Ah[nxt][r][c] = pah[i];
                *(uint2*)&Al[nxt][r][c] = pal[i];
            }
            #pragma unroll
            for (int j = 0; j < 8; j++) {
                Bh[nxt][b_n][b_k0 + j] = pbh[j];
                Bl[nxt][b_n][b_k0 + j] = pbl[j];
            }
        }
        __syncthreads();
    }

    int g = L >> 2, t2 = (L & 3) * 2;
    #pragma unroll
    for (int mf = 0; mf < 4; mf++)
        #pragma unroll
        for (int nf = 0; nf < 4; nf++) {
            int col = n0 + wn * 32 + nf * 8 + t2;
            float2 bv = *(const float2*)&bias[col];
            #pragma unroll
            for (int half = 0; half < 2; half++) {
                int m = m0 + wm * 64 + mf * 16 + g + half * 8;
                float2 rv = *(const float2*)&resid[(size_t)m * CH + col];
                float2 v = make_float2(acc[mf][nf][half*2]   * CINV + bv.x + rv.x,
                                       acc[mf][nf][half*2+1] * CINV + bv.y + rv.y);
                *(float2*)&outp[(size_t)m * CH + col] = v;
            }
        }
}

// ---------------------------------------------------------------------------
// 3) Flash attention, fp16x3, pre-split Q/K/V. P kept in registers
//    (C-fragment == A-fragment layout): no smem round-trip, no P ldsm.
// ---------------------------------------------------------------------------
#define APAD 72

__global__ void f16attn() {
    __shared__ __half Kh[64][APAD], Kl[64][APAD];
    __shared__ __half Vh[64][APAD], Vl[64][APAD];

    int tid = threadIdx.x;
    int w = tid >> 5, L = tid & 31;
    int bh = blockIdx.y;
    int q0 = blockIdx.x * 64;

    size_t hbase = (size_t)bh * SEQ * HD;

    int a_row_off = ((L >> 3) & 1) * 8 + (L & 7);
    int a_col_off = ((L >> 4) & 1) * 8;
    int b_n_off   = ((L >> 4) & 1) * 8 + (L & 7);
    int b_k_off   = ((L >> 3) & 1) * 8;
    int g = L >> 2, t2 = (L & 3) * 2;

    // Stage pre-split Q through Kh/Kl, build persistent fragments
    #pragma unroll
    for (int i = 0; i < 8; i++) {
        int s = tid + i * 128;
        int r = s >> 4, d4 = (s & 15) * 4;
        size_t off = hbase + (size_t)(q0 + r) * HD + d4;
        *(uint2*)&Kh[r][d4] = *(const uint2*)&g_qh[off];
        *(uint2*)&Kl[r][d4] = *(const uint2*)&g_ql[off];
    }
    __syncthreads();
    uint32_t qfh[4][4], qfl[4][4];
    #pragma unroll
    for (int ks = 0; ks < 4; ks++) {
        int row = w * 16 + a_row_off;
        ldsm4(qfh[ks], &Kh[row][ks * 16 + a_col_off]);
        ldsm4(qfl[ks], &Kl[row][ks * 16 + a_col_off]);
    }

    float m0r = -1e30f, m1r = -1e30f, l0 = 0.f, l1 = 0.f;
    float oacc[8][4];
    #pragma unroll
    for (int j = 0; j < 8; j++)
        #pragma unroll
        for (int c = 0; c < 4; c++) oacc[j][c] = 0.f;

    for (int s0 = 0; s0 < SEQ; s0 += 64) {
        __syncthreads();   // previous K/V fully consumed
        #pragma unroll
        for (int i = 0; i < 8; i++) {
            int s = tid + i * 128;
            int kv = s >> 4, d4 = (s & 15) * 4;
            size_t off = hbase + (size_t)(s0 + kv) * HD + d4;
            *(uint2*)&Kh[kv][d4] = *(const uint2*)&g_kh[off];
            *(uint2*)&Kl[kv][d4] = *(const uint2*)&g_kl[off];
            *(uint2*)&Vh[kv][d4] = *(const uint2*)&g_vh[off];
            *(uint2*)&Vl[kv][d4] = *(const uint2*)&g_vl[off];
        }
        __syncthreads();

        // S = (8Q)(8K)^T ; rescale by 0.125/64 after
        float sacc[8][4];
        #pragma unroll
        for (int j = 0; j < 8; j++)
            #pragma unroll
            for (int c = 0; c < 4; c++) sacc[j][c] = 0.f;
        #pragma unroll
        for (int ks = 0; ks < 4; ks++) {
            #pragma unroll
            for (int p = 0; p < 4; p++) {
                int n = p * 16 + b_n_off;
                uint32_t th[4], tl[4];
                ldsm4(th, &Kh[n][ks * 16 + b_k_off]);
                ldsm4(tl, &Kl[n][ks * 16 + b_k_off]);
                #pragma unroll
                for (int q = 0; q < 2; q++) {
                    int j = 2 * p + q;
                    const uint32_t bh2[2] = {th[2*q], th[2*q+1]};
                    const uint32_t bl2[2] = {tl[2*q], tl[2*q+1]};
                    mma_f16(sacc[j], qfh[ks], bh2);
                    mma_f16(sacc[j], qfh[ks], bl2);
                    mma_f16(sacc[j], qfl[ks], bh2);
                }
            }
        }
        #pragma unroll
        for (int j = 0; j < 8; j++)
            #pragma unroll
            for (int c = 0; c < 4; c++) sacc[j][c] *= SMUL;

        // Online softmax on fragments (rows g and g+8 of this warp's 16)
        float mx0 = -1e30f, mx1 = -1e30f;
        #pragma unroll
        for (int j = 0; j < 8; j++) {
            mx0 = fmaxf(mx0, fmaxf(sacc[j][0], sacc[j][1]));
            mx1 = fmaxf(mx1, fmaxf(sacc[j][2], sacc[j][3]));
        }
        #pragma unroll
        for (int o = 1; o <= 2; o <<= 1) {
            mx0 = fmaxf(mx0, __shfl_xor_sync(0xffffffffu, mx0, o));
            mx1 = fmaxf(mx1, __shfl_xor_sync(0xffffffffu, mx1, o));
        }
        float mn0 = fmaxf(m0r, mx0), mn1 = fmaxf(m1r, mx1);
        float f0 = __expf(m0r - mn0), f1 = __expf(m1r - mn1);
        m0r = mn0; m1r = mn1;
        float rs0 = 0.f, rs1 = 0.f;
        #pragma unroll
        for (int j = 0; j < 8; j++) {
            sacc[j][0] = __expf(sacc[j][0] - mn0);
            sacc[j][1] = __expf(sacc[j][1] - mn0);
            sacc[j][2] = __expf(sacc[j][2] - mn1);
            sacc[j][3] = __expf(sacc[j][3] - mn1);
            rs0 += sacc[j][0] + sacc[j][1];
            rs1 += sacc[j][2] + sacc[j][3];
        }
        #pragma unroll
        for (int o = 1; o <= 2; o <<= 1) {
            rs0 += __shfl_xor_sync(0xffffffffu, rs0, o);
            rs1 += __shfl_xor_sync(0xffffffffu, rs1, o);
        }
        l0 = l0 * f0 + rs0;
        l1 = l1 * f1 + rs1;
        #pragma unroll
        for (int j = 0; j < 8; j++) {
            oacc[j][0] *= f0; oacc[j][1] *= f0;
            oacc[j][2] *= f1; oacc[j][3] *= f1;
        }

        // Build P A-fragments in registers: x64 scaling, hi/lo split.
        uint32_t pfh[4][4], pfl[4][4];
        #pragma unroll
        for (int ks = 0; ks < 4; ks++) {
            int j0 = 2 * ks, j1 = 2 * ks + 1;
            pfh[ks][0] = split_h2(sacc[j0][0] * 64.0f, sacc[j0][1] * 64.0f, pfl[ks][0]);
            pfh[ks][1] = split_h2(sacc[j0][2] * 64.0f, sacc[j0][3] * 64.0f, pfl[ks][1]);
            pfh[ks][2] = split_h2(sacc[j1][0] * 64.0f, sacc[j1][1] * 64.0f, pfl[ks][2]);
            pfh[ks][3] = split_h2(sacc[j1][2] * 64.0f, sacc[j1][3] * 64.0f, pfl[ks][3]);
        }

        // O += (64P)(8V)   (V via ldmatrix.trans; P from registers)
        #pragma unroll
        for (int ks = 0; ks < 4; ks++) {
            #pragma unroll
            for (int p = 0; p < 4; p++) {
                uint32_t th[4], tl[4];
                ldsm4t(th, &Vh[ks * 16 + a_row_off][p * 16 + a_col_off]);
                ldsm4t(tl, &Vl[ks * 16 + a_row_off][p * 16 + a_col_off]);
                #pragma unroll
                for (int q = 0; q < 2; q++) {
                    int j = 2 * p + q;
                    const uint32_t bh2[2] = {th[2*q], th[2*q+1]};
                    const uint32_t bl2[2] = {tl[2*q], tl[2*q+1]};
                    mma_f16(oacc[j], pfh[ks], bh2);
                    mma_f16(oacc[j], pfh[ks], bl2);
                    mma_f16(oacc[j], pfl[ks], bh2);
                }
            }
        }
    }

    // Epilogue: o_actual = oacc/(512 l); store split(o_actual*8) = split(oacc/(64 l))
    int b = bh / NH, h = bh % NH;
    float inv0 = (1.0f / 64.0f) / l0, inv1 = (1.0f / 64.0f) / l1;
    #pragma unroll
    for (int j = 0; j < 8; j++) {
        int d = j * 8 + t2;
        int q = q0 + w * 16 + g;
        size_t off0 = ((size_t)(b * SEQ + q)) * CH + h * HD + d;
        size_t off1 = ((size_t)(b * SEQ + q + 8)) * CH + h * HD + d;
        uint32_t lo2;
        uint32_t hi2 = split_h2(oacc[j][0] * inv0, oacc[j][1] * inv0, lo2);
        *(uint32_t*)&g_atth[off0] = hi2;
        *(uint32_t*)&g_attl[off0] = lo2;
        hi2 = split_h2(oacc[j][2] * inv1, oacc[j][3] * inv1, lo2);
        *(uint32_t*)&g_atth[off1] = hi2;
        *(uint32_t*)&g_attl[off1] = lo2;
    }
}

// ---------------------------------------------------------------------------
extern "C" void kernel_launch(void* const* d_in, const int* in_sizes, int n_in,
                              void* d_out, int out_size) {
    const float* img   = (const float*)d_in[0];
    const float* gamma = (const float*)d_in[1];
    const float* beta  = (const float*)d_in[2];
    const float* w_qkv = (const float*)d_in[3];
    const float* w_out = (const float*)d_in[4];
    const float* b_out = (const float*)d_in[5];
    float* out = (float*)d_out;

    __half *wqh, *wql, *woh, *wol;
    cudaGetSymbolAddress((void**)&wqh, g_wqh);
    cudaGetSymbolAddress((void**)&wql, g_wql);
    cudaGetSymbolAddress((void**)&woh, g_woh);
    cudaGetSymbolAddress((void**)&wol, g_wol);

    wsplit_kernel<<<(CH * C3 + 255) / 256, 256>>>(w_qkv, wqh, wql, CH * C3);
    wsplit_kernel<<<(CH * CH + 255) / 256, 256>>>(w_out, woh, wol, CH * CH);
    ln_kernel<<<TOK, 256>>>(img, gamma, beta);
    f16gemm_qkv<<<dim3(C3 / GBN, TOK / GBM), 128>>>();
    f16attn<<<dim3(SEQ / 64, BH), 128>>>();
    f16gemm_out<<<dim3(CH / GBN, TOK / GBM), 128>>>(b_out, img, out);
}

// round 15
// speedup vs baseline: 1.8579x; 1.4944x over previous

#include <cuda_runtime.h>
#include <cuda_fp16.h>
#include <math.h>
#include <stdint.h>

// Problem constants
#define BSZ 4
#define SEQ 2048
#define CH  768
#define NH  12
#define HD  64
#define TOK (BSZ*SEQ)   // 8192
#define C3  (3*CH)      // 2304
#define BH  (BSZ*NH)    // 48

// Pre-split storage (allocation-free per harness rules).
// Activations keep hi only except Q and P (which keep lo for the
// kept correction terms Q_lo*K_hi and P_lo*V_hi). Weights keep hi+lo.
__device__ __half g_xnh[TOK*CH];                     // LN output, x8 (hi only)
__device__ __half g_qh[BH*SEQ*HD], g_ql[BH*SEQ*HD];  // Q, x8 (hi+lo)
__device__ __half g_kh[BH*SEQ*HD];                   // K, x8 (hi only)
__device__ __half g_vh[BH*SEQ*HD];                   // V, x8 (hi only)
__device__ __half g_atth[TOK*CH];                    // attn out, x8 (hi only)
__device__ __half g_wqh[CH*C3],  g_wql[CH*C3];       // w_qkv, x64 (hi+lo)
__device__ __half g_woh[CH*CH],  g_wol[CH*CH];       // w_out, x64 (hi+lo)

#define ASCALE 8.0f
#define WSCALE 64.0f
#define CINV   (1.0f/512.0f)
#define SMUL   (0.125f/64.0f)

// ---------------------------------------------------------------------------
// helpers
// ---------------------------------------------------------------------------
__device__ __forceinline__ void splitf(float x, __half& h, __half& l) {
    h = __float2half_rn(x);
    l = __float2half_rn(x - __half2float(h));
}

__device__ __forceinline__ uint32_t split_h2(float a, float b, uint32_t& lo2) {
    __half ha, la, hbb, lb;
    splitf(a, ha, la);
    splitf(b, hbb, lb);
    __half2 hh = __halves2half2(ha, hbb);
    __half2 ll = __halves2half2(la, lb);
    lo2 = *(uint32_t*)&ll;
    return *(uint32_t*)&hh;
}

__device__ __forceinline__ uint32_t pack_h2(float a, float b) {
    __half2 hh = __halves2half2(__float2half_rn(a), __float2half_rn(b));
    return *(uint32_t*)&hh;
}

__device__ __forceinline__ void ldsm4(uint32_t a[4], const void* p) {
    uint32_t addr = (uint32_t)__cvta_generic_to_shared(p);
    asm volatile("ldmatrix.sync.aligned.m8n8.x4.shared.b16 {%0,%1,%2,%3}, [%4];"
                 : "=r"(a[0]), "=r"(a[1]), "=r"(a[2]), "=r"(a[3]) : "r"(addr));
}

__device__ __forceinline__ void ldsm4t(uint32_t a[4], const void* p) {
    uint32_t addr = (uint32_t)__cvta_generic_to_shared(p);
    asm volatile("ldmatrix.sync.aligned.m8n8.x4.trans.shared.b16 {%0,%1,%2,%3}, [%4];"
                 : "=r"(a[0]), "=r"(a[1]), "=r"(a[2]), "=r"(a[3]) : "r"(addr));
}

__device__ __forceinline__ void mma_f16(float c[4], const uint32_t a[4], const uint32_t b[2]) {
    asm volatile(
        "mma.sync.aligned.m16n8k16.row.col.f32.f16.f16.f32 "
        "{%0,%1,%2,%3},{%4,%5,%6,%7},{%8,%9},{%0,%1,%2,%3};"
        : "+f"(c[0]), "+f"(c[1]), "+f"(c[2]), "+f"(c[3])
        : "r"(a[0]), "r"(a[1]), "r"(a[2]), "r"(a[3]), "r"(b[0]), "r"(b[1]));
}

// ---------------------------------------------------------------------------
// 0) Weight split: dst = split(src * 64)
// ---------------------------------------------------------------------------
__global__ void wsplit_kernel(const float* __restrict__ src,
                              __half* __restrict__ dh,
                              __half* __restrict__ dl,
                              int n) {
    int i = blockIdx.x * 256 + threadIdx.x;
    if (i < n) {
        __half h, lo;
        splitf(src[i] * WSCALE, h, lo);
        dh[i] = h; dl[i] = lo;
    }
}

// ---------------------------------------------------------------------------
// 1) LayerNorm: one block per token; writes hi half only (x8)
// ---------------------------------------------------------------------------
__global__ void ln_kernel(const float* __restrict__ x,
                          const float* __restrict__ gamma,
                          const float* __restrict__ beta) {
    int t = blockIdx.x;
    const float* xr = x + (size_t)t * CH;
    int i0 = threadIdx.x, i1 = i0 + 256, i2 = i0 + 512;
    float v0 = xr[i0], v1 = xr[i1], v2 = xr[i2];
    float s  = v0 + v1 + v2;
    float s2 = v0*v0 + v1*v1 + v2*v2;
    #pragma unroll
    for (int o = 16; o > 0; o >>= 1) {
        s  += __shfl_down_sync(0xffffffffu, s,  o);
        s2 += __shfl_down_sync(0xffffffffu, s2, o);
    }
    __shared__ float ws[8], ws2[8];
    __shared__ float mu_s, inv_s;
    int w = threadIdx.x >> 5, l = threadIdx.x & 31;
    if (l == 0) { ws[w] = s; ws2[w] = s2; }
    __syncthreads();
    if (threadIdx.x == 0) {
        float a = 0.f, b = 0.f;
        #pragma unroll
        for (int k = 0; k < 8; k++) { a += ws[k]; b += ws2[k]; }
        float mu  = a * (1.0f / CH);
        float var = b * (1.0f / CH) - mu * mu;
        mu_s  = mu;
        inv_s = rsqrtf(var + 1e-5f);
    }
    __syncthreads();
    float mu = mu_s, inv = inv_s;
    size_t base = (size_t)t * CH;
    float o0 = (v0 - mu) * inv * gamma[i0] + beta[i0];
    float o1 = (v1 - mu) * inv * gamma[i1] + beta[i1];
    float o2 = (v2 - mu) * inv * gamma[i2] + beta[i2];
    g_xnh[base + i0] = __float2half_rn(o0 * ASCALE);
    g_xnh[base + i1] = __float2half_rn(o1 * ASCALE);
    g_xnh[base + i2] = __float2half_rn(o2 * ASCALE);
}

// ---------------------------------------------------------------------------
// GEMM config: BM=128, BN=64, BK=16, 128 threads = 4 warps (2x2),
// warp tile 64x32. A hi-only; B hi+lo. 2 mma per step: Ah*Bh + Ah*Bl.
// ---------------------------------------------------------------------------
#define GBM 128
#define GBN 64
#define GBK 16
#define HPAD 24

// 2) QKV GEMM: xn_h @ wqkv(split) -> Q (hi+lo), K/V (hi only), all x8
__global__ void f16gemm_qkv() {
    __shared__ __half Ah[2][GBM][HPAD];
    __shared__ __half Bh[2][GBN][HPAD], Bl[2][GBN][HPAD];

    int tid = threadIdx.x;
    int w = tid >> 5, L = tid & 31;
    int wm = w >> 1, wn = w & 1;
    int m0 = blockIdx.y * GBM;
    int n0 = blockIdx.x * GBN;

    float acc[4][4][4];
    #pragma unroll
    for (int i = 0; i < 4; i++)
        #pragma unroll
        for (int j = 0; j < 4; j++)
            #pragma unroll
            for (int c = 0; c < 4; c++) acc[i][j][c] = 0.f;

    int b_n  = tid & 63;
    int b_k0 = (tid >> 6) * 8;
    const int KT = CH / GBK;

    {
        #pragma unroll
        for (int i = 0; i < 4; i++) {
            int s = tid + i * 128;
            int r = s >> 2, c = (s & 3) * 4;
            size_t off = (size_t)(m0 + r) * CH + c;
            *(uint2*)&Ah[0][r][c] = *(const uint2*)&g_xnh[off];
        }
        #pragma unroll
        for (int j = 0; j < 8; j++) {
            size_t off = (size_t)(b_k0 + j) * C3 + n0 + b_n;
            Bh[0][b_n][b_k0 + j] = g_wqh[off];
            Bl[0][b_n][b_k0 + j] = g_wql[off];
        }
    }
    __syncthreads();

    int a_row_off = ((L >> 3) & 1) * 8 + (L & 7);
    int a_col_off = ((L >> 4) & 1) * 8;
    int b_n_off   = ((L >> 4) & 1) * 8 + (L & 7);
    int b_k_off   = ((L >> 3) & 1) * 8;

    for (int kt = 0; kt < KT; kt++) {
        int cur = kt & 1, nxt = cur ^ 1;
        uint2 pah[4];
        __half pbh[8], pbl[8];
        bool has_next = (kt + 1 < KT);
        if (has_next) {
            int kbase = (kt + 1) * GBK;
            #pragma unroll
            for (int i = 0; i < 4; i++) {
                int s = tid + i * 128;
                int r = s >> 2, c = (s & 3) * 4;
                size_t off = (size_t)(m0 + r) * CH + kbase + c;
                pah[i] = *(const uint2*)&g_xnh[off];
            }
            #pragma unroll
            for (int j = 0; j < 8; j++) {
                size_t off = (size_t)(kbase + b_k0 + j) * C3 + n0 + b_n;
                pbh[j] = g_wqh[off];
                pbl[j] = g_wql[off];
            }
        }
        {
            uint32_t afh[4][4];
            #pragma unroll
            for (int mf = 0; mf < 4; mf++) {
                int row = wm * 64 + mf * 16 + a_row_off;
                ldsm4(afh[mf], &Ah[cur][row][a_col_off]);
            }
            #pragma unroll
            for (int p = 0; p < 2; p++) {
                int n = wn * 32 + p * 16 + b_n_off;
                uint32_t th[4], tl[4];
                ldsm4(th, &Bh[cur][n][b_k_off]);
                ldsm4(tl, &Bl[cur][n][b_k_off]);
                #pragma unroll
                for (int q = 0; q < 2; q++) {
                    int nf = 2 * p + q;
                    const uint32_t bh2[2] = {th[2*q], th[2*q+1]};
                    const uint32_t bl2[2] = {tl[2*q], tl[2*q+1]};
                    #pragma unroll
                    for (int mf = 0; mf < 4; mf++) {
                        mma_f16(acc[mf][nf], afh[mf], bh2);
                        mma_f16(acc[mf][nf], afh[mf], bl2);
                    }
                }
            }
        }
        if (has_next) {
            #pragma unroll
            for (int i = 0; i < 4; i++) {
                int s = tid + i * 128;
                int r = s >> 2, c = (s & 3) * 4;
                *(uint2*)&Ah[nxt][r][c] = pah[i];
            }
            #pragma unroll
            for (int j = 0; j < 8; j++) {
                Bh[nxt][b_n][b_k0 + j] = pbh[j];
                Bl[nxt][b_n][b_k0 + j] = pbl[j];
            }
        }
        __syncthreads();
    }

    // epilogue: val = acc/512; store x8 representation = acc/64.
    // Q: hi+lo split; K/V: hi only.
    int g = L >> 2, t2 = (L & 3) * 2;
    int which = n0 / CH;
    int h = (n0 % CH) >> 6;
    __half* dsth = (which == 0) ? g_qh : ((which == 1) ? g_kh : g_vh);
    #pragma unroll
    for (int mf = 0; mf < 4; mf++)
        #pragma unroll
        for (int nf = 0; nf < 4; nf++) {
            int d = wn * 32 + nf * 8 + t2;
            #pragma unroll
            for (int half = 0; half < 2; half++) {
                int m = m0 + wm * 64 + mf * 16 + g + half * 8;
                int b = m >> 11, n = m & (SEQ - 1);
                size_t off = ((size_t)(b * NH + h) * SEQ + n) * HD + d;
                float v0 = acc[mf][nf][half*2]   * (1.0f/64.0f);
                float v1 = acc[mf][nf][half*2+1] * (1.0f/64.0f);
                if (which == 0) {
                    uint32_t lo2;
                    uint32_t hi2 = split_h2(v0, v1, lo2);
                    *(uint32_t*)&dsth[off] = hi2;
                    *(uint32_t*)&g_ql[off] = lo2;
                } else {
                    *(uint32_t*)&dsth[off] = pack_h2(v0, v1);
                }
            }
        }
}

// 4) Output GEMM: att_h @ w_out(split) + bias + residual -> fp32 out
__global__ void f16gemm_out(const float* __restrict__ bias,
                            const float* __restrict__ resid,
                            float* __restrict__ outp) {
    __shared__ __half Ah[2][GBM][HPAD];
    __shared__ __half Bh[2][GBN][HPAD], Bl[2][GBN][HPAD];

    int tid = threadIdx.x;
    int w = tid >> 5, L = tid & 31;
    int wm = w >> 1, wn = w & 1;
    int m0 = blockIdx.y * GBM;
    int n0 = blockIdx.x * GBN;

    float acc[4][4][4];
    #pragma unroll
    for (int i = 0; i < 4; i++)
        #pragma unroll
        for (int j = 0; j < 4; j++)
            #pragma unroll
            for (int c = 0; c < 4; c++) acc[i][j][c] = 0.f;

    int b_n  = tid & 63;
    int b_k0 = (tid >> 6) * 8;
    const int KT = CH / GBK;

    {
        #pragma unroll
        for (int i = 0; i < 4; i++) {
            int s = tid + i * 128;
            int r = s >> 2, c = (s & 3) * 4;
            size_t off = (size_t)(m0 + r) * CH + c;
            *(uint2*)&Ah[0][r][c] = *(const uint2*)&g_atth[off];
        }
        #pragma unroll
        for (int j = 0; j < 8; j++) {
            size_t off = (size_t)(b_k0 + j) * CH + n0 + b_n;
            Bh[0][b_n][b_k0 + j] = g_woh[off];
            Bl[0][b_n][b_k0 + j] = g_wol[off];
        }
    }
    __syncthreads();

    int a_row_off = ((L >> 3) & 1) * 8 + (L & 7);
    int a_col_off = ((L >> 4) & 1) * 8;
    int b_n_off   = ((L >> 4) & 1) * 8 + (L & 7);
    int b_k_off   = ((L >> 3) & 1) * 8;

    for (int kt = 0; kt < KT; kt++) {
        int cur = kt & 1, nxt = cur ^ 1;
        uint2 pah[4];
        __half pbh[8], pbl[8];
        bool has_next = (kt + 1 < KT);
        if (has_next) {
            int kbase = (kt + 1) * GBK;
            #pragma unroll
            for (int i = 0; i < 4; i++) {
                int s = tid + i * 128;
                int r = s >> 2, c = (s & 3) * 4;
                size_t off = (size_t)(m0 + r) * CH + kbase + c;
                pah[i] = *(const uint2*)&g_atth[off];
            }
            #pragma unroll
            for (int j = 0; j < 8; j++) {
                size_t off = (size_t)(kbase + b_k0 + j) * CH + n0 + b_n;
                pbh[j] = g_woh[off];
                pbl[j] = g_wol[off];
            }
        }
        {
            uint32_t afh[4][4];
            #pragma unroll
            for (int mf = 0; mf < 4; mf++) {
                int row = wm * 64 + mf * 16 + a_row_off;
                ldsm4(afh[mf], &Ah[cur][row][a_col_off]);
            }
            #pragma unroll
            for (int p = 0; p < 2; p++) {
                int n = wn * 32 + p * 16 + b_n_off;
                uint32_t th[4], tl[4];
                ldsm4(th, &Bh[cur][n][b_k_off]);
                ldsm4(tl, &Bl[cur][n][b_k_off]);
                #pragma unroll
                for (int q = 0; q < 2; q++) {
                    int nf = 2 * p + q;
                    const uint32_t bh2[2] = {th[2*q], th[2*q+1]};
                    const uint32_t bl2[2] = {tl[2*q], tl[2*q+1]};
                    #pragma unroll
                    for (int mf = 0; mf < 4; mf++) {
                        mma_f16(acc[mf][nf], afh[mf], bh2);
                        mma_f16(acc[mf][nf], afh[mf], bl2);
                    }
                }
            }
        }
        if (has_next) {
            #pragma unroll
            for (int i = 0; i < 4; i++) {
                int s = tid + i * 128;
                int r = s >> 2, c = (s & 3) * 4;
                *(uint2*)&Ah[nxt][r][c] = pah[i];
            }
            #pragma unroll
            for (int j = 0; j < 8; j++) {
                Bh[nxt][b_n][b_k0 + j] = pbh[j];
                Bl[nxt][b_n][b_k0 + j] = pbl[j];
            }
        }
        __syncthreads();
    }

    int g = L >> 2, t2 = (L & 3) * 2;
    #pragma unroll
    for (int mf = 0; mf < 4; mf++)
        #pragma unroll
        for (int nf = 0; nf < 4; nf++) {
            int col = n0 + wn * 32 + nf * 8 + t2;
            float2 bv = *(const float2*)&bias[col];
            #pragma unroll
            for (int half = 0; half < 2; half++) {
                int m = m0 + wm * 64 + mf * 16 + g + half * 8;
                float2 rv = *(const float2*)&resid[(size_t)m * CH + col];
                float2 v = make_float2(acc[mf][nf][half*2]   * CINV + bv.x + rv.x,
                                       acc[mf][nf][half*2+1] * CINV + bv.y + rv.y);
                *(float2*)&outp[(size_t)m * CH + col] = v;
            }
        }
}

// ---------------------------------------------------------------------------
// 3) Flash attention: Q hi+lo (persistent frags), K/V hi only, P hi+lo in
//    registers. S = Qh*Kh + Ql*Kh; O += Ph*Vh + Pl*Vh. K/V smem halved.
// ---------------------------------------------------------------------------
#define APAD 72

__global__ void f16attn() {
    __shared__ __half Kh[64][APAD];
    __shared__ __half Vh[64][APAD];

    int tid = threadIdx.x;
    int w = tid >> 5, L = tid & 31;
    int bh = blockIdx.y;
    int q0 = blockIdx.x * 64;

    size_t hbase = (size_t)bh * SEQ * HD;

    int a_row_off = ((L >> 3) & 1) * 8 + (L & 7);
    int a_col_off = ((L >> 4) & 1) * 8;
    int b_n_off   = ((L >> 4) & 1) * 8 + (L & 7);
    int b_k_off   = ((L >> 3) & 1) * 8;
    int g = L >> 2, t2 = (L & 3) * 2;

    // Stage Q hi into Kh and Q lo into Vh; build persistent fragments
    #pragma unroll
    for (int i = 0; i < 8; i++) {
        int s = tid + i * 128;
        int r = s >> 4, d4 = (s & 15) * 4;
        size_t off = hbase + (size_t)(q0 + r) * HD + d4;
        *(uint2*)&Kh[r][d4] = *(const uint2*)&g_qh[off];
        *(uint2*)&Vh[r][d4] = *(const uint2*)&g_ql[off];
    }
    __syncthreads();
    uint32_t qfh[4][4], qfl[4][4];
    #pragma unroll
    for (int ks = 0; ks < 4; ks++) {
        int row = w * 16 + a_row_off;
        ldsm4(qfh[ks], &Kh[row][ks * 16 + a_col_off]);
        ldsm4(qfl[ks], &Vh[row][ks * 16 + a_col_off]);
    }

    float m0r = -1e30f, m1r = -1e30f, l0 = 0.f, l1 = 0.f;
    float oacc[8][4];
    #pragma unroll
    for (int j = 0; j < 8; j++)
        #pragma unroll
        for (int c = 0; c < 4; c++) oacc[j][c] = 0.f;

    for (int s0 = 0; s0 < SEQ; s0 += 64) {
        __syncthreads();   // previous K/V (or Q staging) fully consumed
        #pragma unroll
        for (int i = 0; i < 8; i++) {
            int s = tid + i * 128;
            int kv = s >> 4, d4 = (s & 15) * 4;
            size_t off = hbase + (size_t)(s0 + kv) * HD + d4;
            *(uint2*)&Kh[kv][d4] = *(const uint2*)&g_kh[off];
            *(uint2*)&Vh[kv][d4] = *(const uint2*)&g_vh[off];
        }
        __syncthreads();

        // S = (8Q)(8K)^T with Qh+Ql vs Kh; rescale by 0.125/64 after
        float sacc[8][4];
        #pragma unroll
        for (int j = 0; j < 8; j++)
            #pragma unroll
            for (int c = 0; c < 4; c++) sacc[j][c] = 0.f;
        #pragma unroll
        for (int ks = 0; ks < 4; ks++) {
            #pragma unroll
            for (int p = 0; p < 4; p++) {
                int n = p * 16 + b_n_off;
                uint32_t th[4];
                ldsm4(th, &Kh[n][ks * 16 + b_k_off]);
                #pragma unroll
                for (int q = 0; q < 2; q++) {
                    int j = 2 * p + q;
                    const uint32_t bh2[2] = {th[2*q], th[2*q+1]};
                    mma_f16(sacc[j], qfh[ks], bh2);
                    mma_f16(sacc[j], qfl[ks], bh2);
                }
            }
        }
        #pragma unroll
        for (int j = 0; j < 8; j++)
            #pragma unroll
            for (int c = 0; c < 4; c++) sacc[j][c] *= SMUL;

        // Online softmax on fragments (rows g and g+8 of this warp's 16)
        float mx0 = -1e30f, mx1 = -1e30f;
        #pragma unroll
        for (int j = 0; j < 8; j++) {
            mx0 = fmaxf(mx0, fmaxf(sacc[j][0], sacc[j][1]));
            mx1 = fmaxf(mx1, fmaxf(sacc[j][2], sacc[j][3]));
        }
        #pragma unroll
        for (int o = 1; o <= 2; o <<= 1) {
            mx0 = fmaxf(mx0, __shfl_xor_sync(0xffffffffu, mx0, o));
            mx1 = fmaxf(mx1, __shfl_xor_sync(0xffffffffu, mx1, o));
        }
        float mn0 = fmaxf(m0r, mx0), mn1 = fmaxf(m1r, mx1);
        float f0 = __expf(m0r - mn0), f1 = __expf(m1r - mn1);
        m0r = mn0; m1r = mn1;
        float rs0 = 0.f, rs1 = 0.f;
        #pragma unroll
        for (int j = 0; j < 8; j++) {
            sacc[j][0] = __expf(sacc[j][0] - mn0);
            sacc[j][1] = __expf(sacc[j][1] - mn0);
            sacc[j][2] = __expf(sacc[j][2] - mn1);
            sacc[j][3] = __expf(sacc[j][3] - mn1);
            rs0 += sacc[j][0] + sacc[j][1];
            rs1 += sacc[j][2] + sacc[j][3];
        }
        #pragma unroll
        for (int o = 1; o <= 2; o <<= 1) {
            rs0 += __shfl_xor_sync(0xffffffffu, rs0, o);
            rs1 += __shfl_xor_sync(0xffffffffu, rs1, o);
        }
        l0 = l0 * f0 + rs0;
        l1 = l1 * f1 + rs1;
        #pragma unroll
        for (int j = 0; j < 8; j++) {
            oacc[j][0] *= f0; oacc[j][1] *= f0;
            oacc[j][2] *= f1; oacc[j][3] *= f1;
        }

        // Build P A-fragments in registers: x64 scaling, hi/lo split.
        uint32_t pfh[4][4], pfl[4][4];
        #pragma unroll
        for (int ks = 0; ks < 4; ks++) {
            int j0 = 2 * ks, j1 = 2 * ks + 1;
            pfh[ks][0] = split_h2(sacc[j0][0] * 64.0f, sacc[j0][1] * 64.0f, pfl[ks][0]);
            pfh[ks][1] = split_h2(sacc[j0][2] * 64.0f, sacc[j0][3] * 64.0f, pfl[ks][1]);
            pfh[ks][2] = split_h2(sacc[j1][0] * 64.0f, sacc[j1][1] * 64.0f, pfl[ks][2]);
            pfh[ks][3] = split_h2(sacc[j1][2] * 64.0f, sacc[j1][3] * 64.0f, pfl[ks][3]);
        }

        // O += (64P)(8V) with Ph+Pl vs Vh (V via ldmatrix.trans)
        #pragma unroll
        for (int ks = 0; ks < 4; ks++) {
            #pragma unroll
            for (int p = 0; p < 4; p++) {
                uint32_t th[4];
                ldsm4t(th, &Vh[ks * 16 + a_row_off][p * 16 + a_col_off]);
                #pragma unroll
                for (int q = 0; q < 2; q++) {
                    int j = 2 * p + q;
                    const uint32_t bh2[2] = {th[2*q], th[2*q+1]};
                    mma_f16(oacc[j], pfh[ks], bh2);
                    mma_f16(oacc[j], pfl[ks], bh2);
                }
            }
        }
    }

    // Epilogue: o_actual = oacc/(512 l); store hi-only x8 = fp16(oacc/(64 l))
    int b = bh / NH, h = bh % NH;
    float inv0 = (1.0f / 64.0f) / l0, inv1 = (1.0f / 64.0f) / l1;
    #pragma unroll
    for (int j = 0; j < 8; j++) {
        int d = j * 8 + t2;
        int q = q0 + w * 16 + g;
        size_t off0 = ((size_t)(b * SEQ + q)) * CH + h * HD + d;
        size_t off1 = ((size_t)(b * SEQ + q + 8)) * CH + h * HD + d;
        *(uint32_t*)&g_atth[off0] = pack_h2(oacc[j][0] * inv0, oacc[j][1] * inv0);
        *(uint32_t*)&g_atth[off1] = pack_h2(oacc[j][2] * inv1, oacc[j][3] * inv1);
    }
}

// ---------------------------------------------------------------------------
extern "C" void kernel_launch(void* const* d_in, const int* in_sizes, int n_in,
                              void* d_out, int out_size) {
    const float* img   = (const float*)d_in[0];
    const float* gamma = (const float*)d_in[1];
    const float* beta  = (const float*)d_in[2];
    const float* w_qkv = (const float*)d_in[3];
    const float* w_out = (const float*)d_in[4];
    const float* b_out = (const float*)d_in[5];
    float* out = (float*)d_out;

    __half *wqh, *wql, *woh, *wol;
    cudaGetSymbolAddress((void**)&wqh, g_wqh);
    cudaGetSymbolAddress((void**)&wql, g_wql);
    cudaGetSymbolAddress((void**)&woh, g_woh);
    cudaGetSymbolAddress((void**)&wol, g_wol);

    wsplit_kernel<<<(CH * C3 + 255) / 256, 256>>>(w_qkv, wqh, wql, CH * C3);
    wsplit_kernel<<<(CH * CH + 255) / 256, 256>>>(w_out, woh, wol, CH * CH);
    ln_kernel<<<TOK, 256>>>(img, gamma, beta);
    f16gemm_qkv<<<dim3(C3 / GBN, TOK / GBM), 128>>>();
    f16attn<<<dim3(SEQ / 64, BH), 128>>>();
    f16gemm_out<<<dim3(CH / GBN, TOK / GBM), 128>>>(b_out, img, out);
}

// round 16
// speedup vs baseline: 2.6664x; 1.4351x over previous

#include <cuda_runtime.h>
#include <cuda_fp16.h>
#include <math.h>
#include <stdint.h>

// Problem constants
#define BSZ 4
#define SEQ 2048
#define CH  768
#define NH  12
#define HD  64
#define TOK (BSZ*SEQ)   // 8192
#define C3  (3*CH)      // 2304
#define BH  (BSZ*NH)    // 48

// Storage (allocation-free per harness rules)
__device__ __half g_xnh[TOK*CH];                     // LN output, x8 (hi only)
__device__ __half g_qh[BH*SEQ*HD];                   // Q, x8 (hi only)
__device__ __half g_kh[BH*SEQ*HD];                   // K, x8 (hi only)
__device__ __half g_vh[BH*SEQ*HD];                   // V, x8 (hi only)
__device__ __half g_atth[TOK*CH];                    // attn out, x8 (hi only)
// Prepacked weight fragments (mma B-frag order): [tk][tn][lane] -> uint2
__device__ uint2 g_wqph[(CH/16)*(C3/8)*32], g_wqpl[(CH/16)*(C3/8)*32];
__device__ uint2 g_woph[(CH/16)*(CH/8)*32], g_wopl[(CH/16)*(CH/8)*32];

#define ASCALE 8.0f
#define WSCALE 64.0f
#define CINV   (1.0f/512.0f)
#define SMUL   (0.125f/64.0f)

// ---------------------------------------------------------------------------
// helpers
// ---------------------------------------------------------------------------
__device__ __forceinline__ void splitf(float x, __half& h, __half& l) {
    h = __float2half_rn(x);
    l = __float2half_rn(x - __half2float(h));
}

__device__ __forceinline__ uint32_t split_h2(float a, float b, uint32_t& lo2) {
    __half ha, la, hbb, lb;
    splitf(a, ha, la);
    splitf(b, hbb, lb);
    __half2 hh = __halves2half2(ha, hbb);
    __half2 ll = __halves2half2(la, lb);
    lo2 = *(uint32_t*)&ll;
    return *(uint32_t*)&hh;
}

__device__ __forceinline__ uint32_t pack_h2(float a, float b) {
    __half2 hh = __halves2half2(__float2half_rn(a), __float2half_rn(b));
    return *(uint32_t*)&hh;
}

__device__ __forceinline__ void ldsm4(uint32_t a[4], const void* p) {
    uint32_t addr = (uint32_t)__cvta_generic_to_shared(p);
    asm volatile("ldmatrix.sync.aligned.m8n8.x4.shared.b16 {%0,%1,%2,%3}, [%4];"
                 : "=r"(a[0]), "=r"(a[1]), "=r"(a[2]), "=r"(a[3]) : "r"(addr));
}

__device__ __forceinline__ void ldsm4t(uint32_t a[4], const void* p) {
    uint32_t addr = (uint32_t)__cvta_generic_to_shared(p);
    asm volatile("ldmatrix.sync.aligned.m8n8.x4.trans.shared.b16 {%0,%1,%2,%3}, [%4];"
                 : "=r"(a[0]), "=r"(a[1]), "=r"(a[2]), "=r"(a[3]) : "r"(addr));
}

__device__ __forceinline__ void mma_f16(float c[4], const uint32_t a[4], const uint32_t b[2]) {
    asm volatile(
        "mma.sync.aligned.m16n8k16.row.col.f32.f16.f16.f32 "
        "{%0,%1,%2,%3},{%4,%5,%6,%7},{%8,%9},{%0,%1,%2,%3};"
        : "+f"(c[0]), "+f"(c[1]), "+f"(c[2]), "+f"(c[3])
        : "r"(a[0]), "r"(a[1]), "r"(a[2]), "r"(a[3]), "r"(b[0]), "r"(b[1]));
}

// ---------------------------------------------------------------------------
// 0) Weight pack: split(src*64) written in mma B-fragment order.
//    Frag (tk,tn): lane L holds halves (k=16tk+(L&3)*2+8r +{0,1}, n=8tn+L/4)
//    for r=0 (.x) and r=1 (.y).
// ---------------------------------------------------------------------------
__global__ void wpack_kernel(const float* __restrict__ src,
                             uint2* __restrict__ dh,
                             uint2* __restrict__ dl,
                             int N, int total) {
    int i = blockIdx.x * 256 + threadIdx.x;
    if (i >= total) return;
    int L = i & 31;
    int t = i >> 5;
    int tn = t % (N >> 3), tk = t / (N >> 3);
    int n  = tn * 8 + (L >> 2);
    int k0 = tk * 16 + (L & 3) * 2;
    float w00 = src[(size_t)(k0 + 0) * N + n] * WSCALE;
    float w01 = src[(size_t)(k0 + 1) * N + n] * WSCALE;
    float w10 = src[(size_t)(k0 + 8) * N + n] * WSCALE;
    float w11 = src[(size_t)(k0 + 9) * N + n] * WSCALE;
    uint32_t l0, l1;
    uint32_t h0 = split_h2(w00, w01, l0);
    uint32_t h1 = split_h2(w10, w11, l1);
    dh[i] = make_uint2(h0, h1);
    dl[i] = make_uint2(l0, l1);
}

// ---------------------------------------------------------------------------
// 1) LayerNorm: one block per token; writes hi half only (x8)
// ---------------------------------------------------------------------------
__global__ void ln_kernel(const float* __restrict__ x,
                          const float* __restrict__ gamma,
                          const float* __restrict__ beta) {
    int t = blockIdx.x;
    const float* xr = x + (size_t)t * CH;
    int i0 = threadIdx.x, i1 = i0 + 256, i2 = i0 + 512;
    float v0 = xr[i0], v1 = xr[i1], v2 = xr[i2];
    float s  = v0 + v1 + v2;
    float s2 = v0*v0 + v1*v1 + v2*v2;
    #pragma unroll
    for (int o = 16; o > 0; o >>= 1) {
        s  += __shfl_down_sync(0xffffffffu, s,  o);
        s2 += __shfl_down_sync(0xffffffffu, s2, o);
    }
    __shared__ float ws[8], ws2[8];
    __shared__ float mu_s, inv_s;
    int w = threadIdx.x >> 5, l = threadIdx.x & 31;
    if (l == 0) { ws[w] = s; ws2[w] = s2; }
    __syncthreads();
    if (threadIdx.x == 0) {
        float a = 0.f, b = 0.f;
        #pragma unroll
        for (int k = 0; k < 8; k++) { a += ws[k]; b += ws2[k]; }
        float mu  = a * (1.0f / CH);
        float var = b * (1.0f / CH) - mu * mu;
        mu_s  = mu;
        inv_s = rsqrtf(var + 1e-5f);
    }
    __syncthreads();
    float mu = mu_s, inv = inv_s;
    size_t base = (size_t)t * CH;
    float o0 = (v0 - mu) * inv * gamma[i0] + beta[i0];
    float o1 = (v1 - mu) * inv * gamma[i1] + beta[i1];
    float o2 = (v2 - mu) * inv * gamma[i2] + beta[i2];
    g_xnh[base + i0] = __float2half_rn(o0 * ASCALE);
    g_xnh[base + i1] = __float2half_rn(o1 * ASCALE);
    g_xnh[base + i2] = __float2half_rn(o2 * ASCALE);
}

// ---------------------------------------------------------------------------
// GEMM config: BM=128, BN=64, BK=16, 128 threads = 4 warps (2x2),
// warp tile 64x32. A hi via smem+ldsm; B frags direct from gmem (prepacked),
// software-pipelined one k-tile ahead. 2 mma per step: Ah*Bh + Ah*Bl.
// ---------------------------------------------------------------------------
#define GBM 128
#define GBN 64
#define GBK 16
#define HPAD 24

// 2) QKV GEMM: xn_h @ wqkv(packed) -> Q/K/V hi-only, x8
__global__ void f16gemm_qkv() {
    __shared__ __half Ah[2][GBM][HPAD];

    int tid = threadIdx.x;
    int w = tid >> 5, L = tid & 31;
    int wm = w >> 1, wn = w & 1;
    int m0 = blockIdx.y * GBM;
    int n0 = blockIdx.x * GBN;

    float acc[4][4][4];
    #pragma unroll
    for (int i = 0; i < 4; i++)
        #pragma unroll
        for (int j = 0; j < 4; j++)
            #pragma unroll
            for (int c = 0; c < 4; c++) acc[i][j][c] = 0.f;

    const int KT = CH / GBK;
    const int TNW = C3 >> 3;
    int tnb = (n0 + wn * 32) >> 3;   // first of 4 n8-tiles for this warp

    // prologue: A tile 0 into buf 0; B frags for kt=0
    {
        #pragma unroll
        for (int i = 0; i < 4; i++) {
            int s = tid + i * 128;
            int r = s >> 2, c = (s & 3) * 4;
            size_t off = (size_t)(m0 + r) * CH + c;
            *(uint2*)&Ah[0][r][c] = *(const uint2*)&g_xnh[off];
        }
    }
    uint2 bfh[4], bfl[4];
    #pragma unroll
    for (int t = 0; t < 4; t++) {
        size_t p = ((size_t)0 * TNW + tnb + t) * 32 + L;
        bfh[t] = g_wqph[p];
        bfl[t] = g_wqpl[p];
    }
    __syncthreads();

    int a_row_off = ((L >> 3) & 1) * 8 + (L & 7);
    int a_col_off = ((L >> 4) & 1) * 8;

    for (int kt = 0; kt < KT; kt++) {
        int cur = kt & 1, nxt = cur ^ 1;
        uint2 pah[4];
        uint2 nbh[4], nbl[4];
        bool has_next = (kt + 1 < KT);
        if (has_next) {
            int kbase = (kt + 1) * GBK;
            #pragma unroll
            for (int i = 0; i < 4; i++) {
                int s = tid + i * 128;
                int r = s >> 2, c = (s & 3) * 4;
                size_t off = (size_t)(m0 + r) * CH + kbase + c;
                pah[i] = *(const uint2*)&g_xnh[off];
            }
            #pragma unroll
            for (int t = 0; t < 4; t++) {
                size_t p = ((size_t)(kt + 1) * TNW + tnb + t) * 32 + L;
                nbh[t] = g_wqph[p];
                nbl[t] = g_wqpl[p];
            }
        }
        {
            uint32_t afh[4][4];
            #pragma unroll
            for (int mf = 0; mf < 4; mf++) {
                int row = wm * 64 + mf * 16 + a_row_off;
                ldsm4(afh[mf], &Ah[cur][row][a_col_off]);
            }
            #pragma unroll
            for (int nf = 0; nf < 4; nf++) {
                const uint32_t bh2[2] = {bfh[nf].x, bfh[nf].y};
                const uint32_t bl2[2] = {bfl[nf].x, bfl[nf].y};
                #pragma unroll
                for (int mf = 0; mf < 4; mf++) {
                    mma_f16(acc[mf][nf], afh[mf], bh2);
                    mma_f16(acc[mf][nf], afh[mf], bl2);
                }
            }
        }
        if (has_next) {
            #pragma unroll
            for (int i = 0; i < 4; i++) {
                int s = tid + i * 128;
                int r = s >> 2, c = (s & 3) * 4;
                *(uint2*)&Ah[nxt][r][c] = pah[i];
            }
            #pragma unroll
            for (int t = 0; t < 4; t++) { bfh[t] = nbh[t]; bfl[t] = nbl[t]; }
        }
        __syncthreads();
    }

    // epilogue: val = acc/512; store hi-only x8 = fp16(acc/64)
    int g = L >> 2, t2 = (L & 3) * 2;
    int which = n0 / CH;
    int h = (n0 % CH) >> 6;
    __half* dsth = (which == 0) ? g_qh : ((which == 1) ? g_kh : g_vh);
    #pragma unroll
    for (int mf = 0; mf < 4; mf++)
        #pragma unroll
        for (int nf = 0; nf < 4; nf++) {
            int d = wn * 32 + nf * 8 + t2;
            #pragma unroll
            for (int half = 0; half < 2; half++) {
                int m = m0 + wm * 64 + mf * 16 + g + half * 8;
                int b = m >> 11, n = m & (SEQ - 1);
                size_t off = ((size_t)(b * NH + h) * SEQ + n) * HD + d;
                *(uint32_t*)&dsth[off] = pack_h2(acc[mf][nf][half*2]   * (1.0f/64.0f),
                                                 acc[mf][nf][half*2+1] * (1.0f/64.0f));
            }
        }
}

// 4) Output GEMM: att_h @ w_out(packed) + bias + residual -> fp32 out
__global__ void f16gemm_out(const float* __restrict__ bias,
                            const float* __restrict__ resid,
                            float* __restrict__ outp) {
    __shared__ __half Ah[2][GBM][HPAD];

    int tid = threadIdx.x;
    int w = tid >> 5, L = tid & 31;
    int wm = w >> 1, wn = w & 1;
    int m0 = blockIdx.y * GBM;
    int n0 = blockIdx.x * GBN;

    float acc[4][4][4];
    #pragma unroll
    for (int i = 0; i < 4; i++)
        #pragma unroll
        for (int j = 0; j < 4; j++)
            #pragma unroll
            for (int c = 0; c < 4; c++) acc[i][j][c] = 0.f;

    const int KT = CH / GBK;
    const int TNW = CH >> 3;
    int tnb = (n0 + wn * 32) >> 3;

    {
        #pragma unroll
        for (int i = 0; i < 4; i++) {
            int s = tid + i * 128;
            int r = s >> 2, c = (s & 3) * 4;
            size_t off = (size_t)(m0 + r) * CH + c;
            *(uint2*)&Ah[0][r][c] = *(const uint2*)&g_atth[off];
        }
    }
    uint2 bfh[4], bfl[4];
    #pragma unroll
    for (int t = 0; t < 4; t++) {
        size_t p = ((size_t)0 * TNW + tnb + t) * 32 + L;
        bfh[t] = g_woph[p];
        bfl[t] = g_wopl[p];
    }
    __syncthreads();

    int a_row_off = ((L >> 3) & 1) * 8 + (L & 7);
    int a_col_off = ((L >> 4) & 1) * 8;

    for (int kt = 0; kt < KT; kt++) {
        int cur = kt & 1, nxt = cur ^ 1;
        uint2 pah[4];
        uint2 nbh[4], nbl[4];
        bool has_next = (kt + 1 < KT);
        if (has_next) {
            int kbase = (kt + 1) * GBK;
            #pragma unroll
            for (int i = 0; i < 4; i++) {
                int s = tid + i * 128;
                int r = s >> 2, c = (s & 3) * 4;
                size_t off = (size_t)(m0 + r) * CH + kbase + c;
                pah[i] = *(const uint2*)&g_atth[off];
            }
            #pragma unroll
            for (int t = 0; t < 4; t++) {
                size_t p = ((size_t)(kt + 1) * TNW + tnb + t) * 32 + L;
                nbh[t] = g_woph[p];
                nbl[t] = g_wopl[p];
            }
        }
        {
            uint32_t afh[4][4];
            #pragma unroll
            for (int mf = 0; mf < 4; mf++) {
                int row = wm * 64 + mf * 16 + a_row_off;
                ldsm4(afh[mf], &Ah[cur][row][a_col_off]);
            }
            #pragma unroll
            for (int nf = 0; nf < 4; nf++) {
                const uint32_t bh2[2] = {bfh[nf].x, bfh[nf].y};
                const uint32_t bl2[2] = {bfl[nf].x, bfl[nf].y};
                #pragma unroll
                for (int mf = 0; mf < 4; mf++) {
                    mma_f16(acc[mf][nf], afh[mf], bh2);
                    mma_f16(acc[mf][nf], afh[mf], bl2);
                }
            }
        }
        if (has_next) {
            #pragma unroll
            for (int i = 0; i < 4; i++) {
                int s = tid + i * 128;
                int r = s >> 2, c = (s & 3) * 4;
                *(uint2*)&Ah[nxt][r][c] = pah[i];
            }
            #pragma unroll
            for (int t = 0; t < 4; t++) { bfh[t] = nbh[t]; bfl[t] = nbl[t]; }
        }
        __syncthreads();
    }

    int g = L >> 2, t2 = (L & 3) * 2;
    #pragma unroll
    for (int mf = 0; mf < 4; mf++)
        #pragma unroll
        for (int nf = 0; nf < 4; nf++) {
            int col = n0 + wn * 32 + nf * 8 + t2;
            float2 bv = *(const float2*)&bias[col];
            #pragma unroll
            for (int half = 0; half < 2; half++) {
                int m = m0 + wm * 64 + mf * 16 + g + half * 8;
                float2 rv = *(const float2*)&resid[(size_t)m * CH + col];
                float2 v = make_float2(acc[mf][nf][half*2]   * CINV + bv.x + rv.x,
                                       acc[mf][nf][half*2+1] * CINV + bv.y + rv.y);
                *(float2*)&outp[(size_t)m * CH + col] = v;
            }
        }
}

// ---------------------------------------------------------------------------
// 3) Flash attention, pure fp16 mma (hi only): S = Qh*Kh, O += Ph*Vh.
//    Q frags persistent; P in registers (C-frag == A-frag layout).
// ---------------------------------------------------------------------------
#define APAD 72

__global__ void f16attn() {
    __shared__ __half Kh[64][APAD];
    __shared__ __half Vh[64][APAD];

    int tid = threadIdx.x;
    int w = tid >> 5, L = tid & 31;
    int bh = blockIdx.y;
    int q0 = blockIdx.x * 64;

    size_t hbase = (size_t)bh * SEQ * HD;

    int a_row_off = ((L >> 3) & 1) * 8 + (L & 7);
    int a_col_off = ((L >> 4) & 1) * 8;
    int b_n_off   = ((L >> 4) & 1) * 8 + (L & 7);
    int b_k_off   = ((L >> 3) & 1) * 8;
    int g = L >> 2, t2 = (L & 3) * 2;

    // Stage Q hi into Kh; build persistent fragments
    #pragma unroll
    for (int i = 0; i < 8; i++) {
        int s = tid + i * 128;
        int r = s >> 4, d4 = (s & 15) * 4;
        size_t off = hbase + (size_t)(q0 + r) * HD + d4;
        *(uint2*)&Kh[r][d4] = *(const uint2*)&g_qh[off];
    }
    __syncthreads();
    uint32_t qfh[4][4];
    #pragma unroll
    for (int ks = 0; ks < 4; ks++) {
        int row = w * 16 + a_row_off;
        ldsm4(qfh[ks], &Kh[row][ks * 16 + a_col_off]);
    }

    float m0r = -1e30f, m1r = -1e30f, l0 = 0.f, l1 = 0.f;
    float oacc[8][4];
    #pragma unroll
    for (int j = 0; j < 8; j++)
        #pragma unroll
        for (int c = 0; c < 4; c++) oacc[j][c] = 0.f;

    for (int s0 = 0; s0 < SEQ; s0 += 64) {
        __syncthreads();   // previous K/V (or Q staging) fully consumed
        #pragma unroll
        for (int i = 0; i < 8; i++) {
            int s = tid + i * 128;
            int kv = s >> 4, d4 = (s & 15) * 4;
            size_t off = hbase + (size_t)(s0 + kv) * HD + d4;
            *(uint2*)&Kh[kv][d4] = *(const uint2*)&g_kh[off];
            *(uint2*)&Vh[kv][d4] = *(const uint2*)&g_vh[off];
        }
        __syncthreads();

        // S = (8Q)(8K)^T (hi only); rescale by 0.125/64 after
        float sacc[8][4];
        #pragma unroll
        for (int j = 0; j < 8; j++)
            #pragma unroll
            for (int c = 0; c < 4; c++) sacc[j][c] = 0.f;
        #pragma unroll
        for (int ks = 0; ks < 4; ks++) {
            #pragma unroll
            for (int p = 0; p < 4; p++) {
                int n = p * 16 + b_n_off;
                uint32_t th[4];
                ldsm4(th, &Kh[n][ks * 16 + b_k_off]);
                #pragma unroll
                for (int q = 0; q < 2; q++) {
                    int j = 2 * p + q;
                    const uint32_t bh2[2] = {th[2*q], th[2*q+1]};
                    mma_f16(sacc[j], qfh[ks], bh2);
                }
            }
        }
        #pragma unroll
        for (int j = 0; j < 8; j++)
            #pragma unroll
            for (int c = 0; c < 4; c++) sacc[j][c] *= SMUL;

        // Online softmax on fragments (rows g and g+8 of this warp's 16)
        float mx0 = -1e30f, mx1 = -1e30f;
        #pragma unroll
        for (int j = 0; j < 8; j++) {
            mx0 = fmaxf(mx0, fmaxf(sacc[j][0], sacc[j][1]));
            mx1 = fmaxf(mx1, fmaxf(sacc[j][2], sacc[j][3]));
        }
        #pragma unroll
        for (int o = 1; o <= 2; o <<= 1) {
            mx0 = fmaxf(mx0, __shfl_xor_sync(0xffffffffu, mx0, o));
            mx1 = fmaxf(mx1, __shfl_xor_sync(0xffffffffu, mx1, o));
        }
        float mn0 = fmaxf(m0r, mx0), mn1 = fmaxf(m1r, mx1);
        float f0 = __expf(m0r - mn0), f1 = __expf(m1r - mn1);
        m0r = mn0; m1r = mn1;
        float rs0 = 0.f, rs1 = 0.f;
        #pragma unroll
        for (int j = 0; j < 8; j++) {
            sacc[j][0] = __expf(sacc[j][0] - mn0);
            sacc[j][1] = __expf(sacc[j][1] - mn0);
            sacc[j][2] = __expf(sacc[j][2] - mn1);
            sacc[j][3] = __expf(sacc[j][3] - mn1);
            rs0 += sacc[j][0] + sacc[j][1];
            rs1 += sacc[j][2] + sacc[j][3];
        }
        #pragma unroll
        for (int o = 1; o <= 2; o <<= 1) {
            rs0 += __shfl_xor_sync(0xffffffffu, rs0, o);
            rs1 += __shfl_xor_sync(0xffffffffu, rs1, o);
        }
        l0 = l0 * f0 + rs0;
        l1 = l1 * f1 + rs1;
        #pragma unroll
        for (int j = 0; j < 8; j++) {
            oacc[j][0] *= f0; oacc[j][1] *= f0;
            oacc[j][2] *= f1; oacc[j][3] *= f1;
        }

        // Build P A-fragments in registers (x64, hi only)
        uint32_t pfh[4][4];
        #pragma unroll
        for (int ks = 0; ks < 4; ks++) {
            int j0 = 2 * ks, j1 = 2 * ks + 1;
            pfh[ks][0] = pack_h2(sacc[j0][0] * 64.0f, sacc[j0][1] * 64.0f);
            pfh[ks][1] = pack_h2(sacc[j0][2] * 64.0f, sacc[j0][3] * 64.0f);
            pfh[ks][2] = pack_h2(sacc[j1][0] * 64.0f, sacc[j1][1] * 64.0f);
            pfh[ks][3] = pack_h2(sacc[j1][2] * 64.0f, sacc[j1][3] * 64.0f);
        }

        // O += (64P)(8V) hi only (V via ldmatrix.trans)
        #pragma unroll
        for (int ks = 0; ks < 4; ks++) {
            #pragma unroll
            for (int p = 0; p < 4; p++) {
                uint32_t th[4];
                ldsm4t(th, &Vh[ks * 16 + a_row_off][p * 16 + a_col_off]);
                #pragma unroll
                for (int q = 0; q < 2; q++) {
                    int j = 2 * p + q;
                    const uint32_t bh2[2] = {th[2*q], th[2*q+1]};
                    mma_f16(oacc[j], pfh[ks], bh2);
                }
            }
        }
    }

    // Epilogue: o_actual = oacc/(512 l); store hi-only x8 = fp16(oacc/(64 l))
    int b = bh / NH, h = bh % NH;
    float inv0 = (1.0f / 64.0f) / l0, inv1 = (1.0f / 64.0f) / l1;
    #pragma unroll
    for (int j = 0; j < 8; j++) {
        int d = j * 8 + t2;
        int q = q0 + w * 16 + g;
        size_t off0 = ((size_t)(b * SEQ + q)) * CH + h * HD + d;
        size_t off1 = ((size_t)(b * SEQ + q + 8)) * CH + h * HD + d;
        *(uint32_t*)&g_atth[off0] = pack_h2(oacc[j][0] * inv0, oacc[j][1] * inv0);
        *(uint32_t*)&g_atth[off1] = pack_h2(oacc[j][2] * inv1, oacc[j][3] * inv1);
    }
}

// ---------------------------------------------------------------------------
extern "C" void kernel_launch(void* const* d_in, const int* in_sizes, int n_in,
                              void* d_out, int out_size) {
    const float* img   = (const float*)d_in[0];
    const float* gamma = (const float*)d_in[1];
    const float* beta  = (const float*)d_in[2];
    const float* w_qkv = (const float*)d_in[3];
    const float* w_out = (const float*)d_in[4];
    const float* b_out = (const float*)d_in[5];
    float* out = (float*)d_out;

    uint2 *wqh, *wql, *woh, *wol;
    cudaGetSymbolAddress((void**)&wqh, g_wqph);
    cudaGetSymbolAddress((void**)&wql, g_wqpl);
    cudaGetSymbolAddress((void**)&woh, g_woph);
    cudaGetSymbolAddress((void**)&wol, g_wopl);

    int wq_total = (CH/16)*(C3/8)*32;
    int wo_total = (CH/16)*(CH/8)*32;
    wpack_kernel<<<(wq_total + 255) / 256, 256>>>(w_qkv, wqh, wql, C3, wq_total);
    wpack_kernel<<<(wo_total + 255) / 256, 256>>>(w_out, woh, wol, CH, wo_total);
    ln_kernel<<<TOK, 256>>>(img, gamma, beta);
    f16gemm_qkv<<<dim3(C3 / GBN, TOK / GBM), 128>>>();
    f16attn<<<dim3(SEQ / 64, BH), 128>>>();
    f16gemm_out<<<dim3(CH / GBN, TOK / GBM), 128>>>(b_out, img, out);
}

// round 17
// speedup vs baseline: 2.6688x; 1.0009x over previous

#include <cuda_runtime.h>
#include <cuda_fp16.h>
#include <math.h>
#include <stdint.h>

// Problem constants
#define BSZ 4
#define SEQ 2048
#define CH  768
#define NH  12
#define HD  64
#define TOK (BSZ*SEQ)   // 8192
#define C3  (3*CH)      // 2304
#define BH  (BSZ*NH)    // 48

// Packed fragment storage (allocation-free per harness rules)
// A-frag uint4 layout for X[M,K]: [(m16-tile)*K/16 + (k16-tile)][lane] with
//   .x=X[r][c],.y=X[r+8][c],.z=X[r][c+8],.w=X[r+8][c+8]; r=L>>2, c=(L&3)*2 (+1 packed)
__device__ uint4 g_xnp[(TOK/16)*(CH/16)*32];        // LN out, x8
__device__ uint4 g_qp[BH*(SEQ/16)*4*32];            // Q A-frags per head, x8
__device__ uint2 g_kp[BH*(SEQ/8)*4*32];             // K B-frags per head, x8
__device__ __half g_vh[BH*SEQ*HD];                  // V rows, x8
__device__ uint4 g_attp[(TOK/16)*(CH/16)*32];       // attn out A-frags, x8
// Weight B-frags: [tk][tn][lane] -> uint2 (.x: k=(L&3)*2, .y: k+8; n=L>>2)
__device__ uint2 g_wqph[(CH/16)*(C3/8)*32], g_wqpl[(CH/16)*(C3/8)*32];
__device__ uint2 g_woph[(CH/16)*(CH/8)*32], g_wopl[(CH/16)*(CH/8)*32];

#define ASCALE 8.0f
#define WSCALE 64.0f
#define CINV   (1.0f/512.0f)
#define SMUL   (0.125f/64.0f)
#define QK64   (1.0f/64.0f)

// ---------------------------------------------------------------------------
// helpers
// ---------------------------------------------------------------------------
__device__ __forceinline__ void splitf(float x, __half& h, __half& l) {
    h = __float2half_rn(x);
    l = __float2half_rn(x - __half2float(h));
}

__device__ __forceinline__ uint32_t split_h2(float a, float b, uint32_t& lo2) {
    __half ha, la, hbb, lb;
    splitf(a, ha, la);
    splitf(b, hbb, lb);
    __half2 hh = __halves2half2(ha, hbb);
    __half2 ll = __halves2half2(la, lb);
    lo2 = *(uint32_t*)&ll;
    return *(uint32_t*)&hh;
}

__device__ __forceinline__ uint32_t pack_h2(float a, float b) {
    __half2 hh = __halves2half2(__float2half_rn(a), __float2half_rn(b));
    return *(uint32_t*)&hh;
}

__device__ __forceinline__ void ldsm4t(uint32_t a[4], const void* p) {
    uint32_t addr = (uint32_t)__cvta_generic_to_shared(p);
    asm volatile("ldmatrix.sync.aligned.m8n8.x4.trans.shared.b16 {%0,%1,%2,%3}, [%4];"
                 : "=r"(a[0]), "=r"(a[1]), "=r"(a[2]), "=r"(a[3]) : "r"(addr));
}

__device__ __forceinline__ void mma_f16(float c[4], const uint32_t a[4], const uint32_t b[2]) {
    asm volatile(
        "mma.sync.aligned.m16n8k16.row.col.f32.f16.f16.f32 "
        "{%0,%1,%2,%3},{%4,%5,%6,%7},{%8,%9},{%0,%1,%2,%3};"
        : "+f"(c[0]), "+f"(c[1]), "+f"(c[2]), "+f"(c[3])
        : "r"(a[0]), "r"(a[1]), "r"(a[2]), "r"(a[3]), "r"(b[0]), "r"(b[1]));
}

// ---------------------------------------------------------------------------
// 0) Weight pack (unchanged from r16): split(src*64) in B-frag order
// ---------------------------------------------------------------------------
__global__ void wpack_kernel(const float* __restrict__ src,
                             uint2* __restrict__ dh,
                             uint2* __restrict__ dl,
                             int N, int total) {
    int i = blockIdx.x * 256 + threadIdx.x;
    if (i >= total) return;
    int L = i & 31;
    int t = i >> 5;
    int tn = t % (N >> 3), tk = t / (N >> 3);
    int n  = tn * 8 + (L >> 2);
    int k0 = tk * 16 + (L & 3) * 2;
    float w00 = src[(size_t)(k0 + 0) * N + n] * WSCALE;
    float w01 = src[(size_t)(k0 + 1) * N + n] * WSCALE;
    float w10 = src[(size_t)(k0 + 8) * N + n] * WSCALE;
    float w11 = src[(size_t)(k0 + 9) * N + n] * WSCALE;
    uint32_t l0, l1;
    uint32_t h0 = split_h2(w00, w01, l0);
    uint32_t h1 = split_h2(w10, w11, l1);
    dh[i] = make_uint2(h0, h1);
    dl[i] = make_uint2(l0, l1);
}

// ---------------------------------------------------------------------------
// 1) LayerNorm: one block per token, 384 threads (2 channels each);
//    writes A-fragment layout directly (x8).
// ---------------------------------------------------------------------------
__global__ void ln_kernel(const float* __restrict__ x,
                          const float* __restrict__ gamma,
                          const float* __restrict__ beta) {
    int t = blockIdx.x;
    const float* xr = x + (size_t)t * CH;
    int c0 = threadIdx.x * 2, c1 = c0 + 1;
    float v0 = xr[c0], v1 = xr[c1];
    float s  = v0 + v1;
    float s2 = v0*v0 + v1*v1;
    #pragma unroll
    for (int o = 16; o > 0; o >>= 1) {
        s  += __shfl_down_sync(0xffffffffu, s,  o);
        s2 += __shfl_down_sync(0xffffffffu, s2, o);
    }
    __shared__ float ws[12], ws2[12];
    __shared__ float mu_s, inv_s;
    int w = threadIdx.x >> 5, l = threadIdx.x & 31;
    if (l == 0) { ws[w] = s; ws2[w] = s2; }
    __syncthreads();
    if (threadIdx.x == 0) {
        float a = 0.f, b = 0.f;
        #pragma unroll
        for (int k = 0; k < 12; k++) { a += ws[k]; b += ws2[k]; }
        float mu  = a * (1.0f / CH);
        float var = b * (1.0f / CH) - mu * mu;
        mu_s  = mu;
        inv_s = rsqrtf(var + 1e-5f);
    }
    __syncthreads();
    float mu = mu_s, inv = inv_s;
    float o0 = (v0 - mu) * inv * gamma[c0] + beta[c0];
    float o1 = (v1 - mu) * inv * gamma[c1] + beta[c1];
    // A-frag address for (row t, cols c0,c1)
    int tmq = t >> 4, tk = c0 >> 4;
    int L = ((t & 7) << 2) | ((c0 & 7) >> 1);
    int aidx = ((t & 8) >> 3) | ((c0 & 8) >> 2);
    uint32_t* dst = (uint32_t*)g_xnp;
    dst[(((size_t)tmq * (CH/16) + tk) * 32 + L) * 4 + aidx] =
        pack_h2(o0 * ASCALE, o1 * ASCALE);
}

// ---------------------------------------------------------------------------
// GEMM: no smem, no syncthreads. A frags + B frags streamed from gmem/L2,
// software-pipelined one k-tile ahead. 2 mma per (mf,nf): Ah*Bh + Ah*Bl.
// Block 128 threads = 4 warps (2x2); warp tile 64x32; block tile 128x64.
// ---------------------------------------------------------------------------
#define GBM 128
#define GBN 64

// 2) QKV GEMM -> Q A-frags, K B-frags, V rows (all x8)
__global__ void f16gemm_qkv() {
    int tid = threadIdx.x;
    int w = tid >> 5, L = tid & 31;
    int wm = w >> 1, wn = w & 1;
    int m0 = blockIdx.y * GBM;
    int n0 = blockIdx.x * GBN;

    float acc[4][4][4];
    #pragma unroll
    for (int i = 0; i < 4; i++)
        #pragma unroll
        for (int j = 0; j < 4; j++)
            #pragma unroll
            for (int c = 0; c < 4; c++) acc[i][j][c] = 0.f;

    const int KT = CH / 16;    // 48
    const int TNW = C3 >> 3;   // 288
    int tnb = (n0 + wn * 32) >> 3;
    int tmb[4];
    #pragma unroll
    for (int mf = 0; mf < 4; mf++)
        tmb[mf] = ((m0 + wm * 64 + mf * 16) >> 4) * KT;

    uint4 afc[4]; uint2 bhc[4], blc[4];
    #pragma unroll
    for (int mf = 0; mf < 4; mf++)
        afc[mf] = g_xnp[(size_t)(tmb[mf] + 0) * 32 + L];
    #pragma unroll
    for (int t = 0; t < 4; t++) {
        size_t p = ((size_t)0 * TNW + tnb + t) * 32 + L;
        bhc[t] = g_wqph[p];
        blc[t] = g_wqpl[p];
    }

    for (int kt = 0; kt < KT; kt++) {
        uint4 afn[4]; uint2 bhn[4], bln[4];
        bool hn = (kt + 1 < KT);
        if (hn) {
            #pragma unroll
            for (int mf = 0; mf < 4; mf++)
                afn[mf] = g_xnp[(size_t)(tmb[mf] + kt + 1) * 32 + L];
            #pragma unroll
            for (int t = 0; t < 4; t++) {
                size_t p = ((size_t)(kt + 1) * TNW + tnb + t) * 32 + L;
                bhn[t] = g_wqph[p];
                bln[t] = g_wqpl[p];
            }
        }
        #pragma unroll
        for (int nf = 0; nf < 4; nf++) {
            const uint32_t bh2[2] = {bhc[nf].x, bhc[nf].y};
            const uint32_t bl2[2] = {blc[nf].x, blc[nf].y};
            #pragma unroll
            for (int mf = 0; mf < 4; mf++) {
                mma_f16(acc[mf][nf], (const uint32_t*)&afc[mf], bh2);
                mma_f16(acc[mf][nf], (const uint32_t*)&afc[mf], bl2);
            }
        }
        if (hn) {
            #pragma unroll
            for (int mf = 0; mf < 4; mf++) afc[mf] = afn[mf];
            #pragma unroll
            for (int t = 0; t < 4; t++) { bhc[t] = bhn[t]; blc[t] = bln[t]; }
        }
    }

    // Epilogue: acc x8-representation = acc/64.
    int g = L >> 2, t2 = (L & 3) * 2;
    int which = n0 / CH;
    int h = (n0 % CH) >> 6;
    if (which == 0) {
        // Q as A-frags: [bh][q16-tile][dk 0..3][lane]
        #pragma unroll
        for (int mf = 0; mf < 4; mf++) {
            int m = m0 + wm * 64 + mf * 16;
            int b = m >> 11;
            int nt = (m & (SEQ - 1)) >> 4;
            size_t base = ((size_t)(b * NH + h) * (SEQ/16) + nt) * 4;
            #pragma unroll
            for (int u = 0; u < 2; u++) {
                int dk = wn * 2 + u;
                uint4 v;
                v.x = pack_h2(acc[mf][2*u  ][0] * QK64, acc[mf][2*u  ][1] * QK64);
                v.y = pack_h2(acc[mf][2*u  ][2] * QK64, acc[mf][2*u  ][3] * QK64);
                v.z = pack_h2(acc[mf][2*u+1][0] * QK64, acc[mf][2*u+1][1] * QK64);
                v.w = pack_h2(acc[mf][2*u+1][2] * QK64, acc[mf][2*u+1][3] * QK64);
                g_qp[(base + dk) * 32 + L] = v;
            }
        }
    } else if (which == 1) {
        // K as B-frags: [bh][kv8-tile][dk 0..3][lane]
        #pragma unroll
        for (int mf = 0; mf < 4; mf++) {
            int m = m0 + wm * 64 + mf * 16;
            int b = m >> 11;
            int t8 = (m & (SEQ - 1)) >> 3;
            size_t base = (size_t)(b * NH + h) * (SEQ/8);
            #pragma unroll
            for (int u = 0; u < 2; u++) {
                int dk = wn * 2 + u;
                uint2 b0, b1;
                b0.x = pack_h2(acc[mf][2*u  ][0] * QK64, acc[mf][2*u  ][1] * QK64);
                b0.y = pack_h2(acc[mf][2*u+1][0] * QK64, acc[mf][2*u+1][1] * QK64);
                b1.x = pack_h2(acc[mf][2*u  ][2] * QK64, acc[mf][2*u  ][3] * QK64);
                b1.y = pack_h2(acc[mf][2*u+1][2] * QK64, acc[mf][2*u+1][3] * QK64);
                g_kp[((base + t8    ) * 4 + dk) * 32 + L] = b0;
                g_kp[((base + t8 + 1) * 4 + dk) * 32 + L] = b1;
            }
        }
    } else {
        // V rows (hi only)
        #pragma unroll
        for (int mf = 0; mf < 4; mf++)
            #pragma unroll
            for (int nf = 0; nf < 4; nf++) {
                int d = wn * 32 + nf * 8 + t2;
                #pragma unroll
                for (int half = 0; half < 2; half++) {
                    int m = m0 + wm * 64 + mf * 16 + g + half * 8;
                    int b = m >> 11, n = m & (SEQ - 1);
                    size_t off = ((size_t)(b * NH + h) * SEQ + n) * HD + d;
                    *(uint32_t*)&g_vh[off] =
                        pack_h2(acc[mf][nf][half*2] * QK64, acc[mf][nf][half*2+1] * QK64);
                }
            }
    }
}

// 4) Output GEMM: att A-frags @ w_out B-frags + bias + residual -> fp32
__global__ void f16gemm_out(const float* __restrict__ bias,
                            const float* __restrict__ resid,
                            float* __restrict__ outp) {
    int tid = threadIdx.x;
    int w = tid >> 5, L = tid & 31;
    int wm = w >> 1, wn = w & 1;
    int m0 = blockIdx.y * GBM;
    int n0 = blockIdx.x * GBN;

    float acc[4][4][4];
    #pragma unroll
    for (int i = 0; i < 4; i++)
        #pragma unroll
        for (int j = 0; j < 4; j++)
            #pragma unroll
            for (int c = 0; c < 4; c++) acc[i][j][c] = 0.f;

    const int KT = CH / 16;    // 48
    const int TNW = CH >> 3;   // 96
    int tnb = (n0 + wn * 32) >> 3;
    int tmb[4];
    #pragma unroll
    for (int mf = 0; mf < 4; mf++)
        tmb[mf] = ((m0 + wm * 64 + mf * 16) >> 4) * KT;

    uint4 afc[4]; uint2 bhc[4], blc[4];
    #pragma unroll
    for (int mf = 0; mf < 4; mf++)
        afc[mf] = g_attp[(size_t)(tmb[mf] + 0) * 32 + L];
    #pragma unroll
    for (int t = 0; t < 4; t++) {
        size_t p = ((size_t)0 * TNW + tnb + t) * 32 + L;
        bhc[t] = g_woph[p];
        blc[t] = g_wopl[p];
    }

    for (int kt = 0; kt < KT; kt++) {
        uint4 afn[4]; uint2 bhn[4], bln[4];
        bool hn = (kt + 1 < KT);
        if (hn) {
            #pragma unroll
            for (int mf = 0; mf < 4; mf++)
                afn[mf] = g_attp[(size_t)(tmb[mf] + kt + 1) * 32 + L];
            #pragma unroll
            for (int t = 0; t < 4; t++) {
                size_t p = ((size_t)(kt + 1) * TNW + tnb + t) * 32 + L;
                bhn[t] = g_woph[p];
                bln[t] = g_wopl[p];
            }
        }
        #pragma unroll
        for (int nf = 0; nf < 4; nf++) {
            const uint32_t bh2[2] = {bhc[nf].x, bhc[nf].y};
            const uint32_t bl2[2] = {blc[nf].x, blc[nf].y};
            #pragma unroll
            for (int mf = 0; mf < 4; mf++) {
                mma_f16(acc[mf][nf], (const uint32_t*)&afc[mf], bh2);
                mma_f16(acc[mf][nf], (const uint32_t*)&afc[mf], bl2);
            }
        }
        if (hn) {
            #pragma unroll
            for (int mf = 0; mf < 4; mf++) afc[mf] = afn[mf];
            #pragma unroll
            for (int t = 0; t < 4; t++) { bhc[t] = bhn[t]; blc[t] = bln[t]; }
        }
    }

    int g = L >> 2, t2 = (L & 3) * 2;
    #pragma unroll
    for (int mf = 0; mf < 4; mf++)
        #pragma unroll
        for (int nf = 0; nf < 4; nf++) {
            int col = n0 + wn * 32 + nf * 8 + t2;
            float2 bv = *(const float2*)&bias[col];
            #pragma unroll
            for (int half = 0; half < 2; half++) {
                int m = m0 + wm * 64 + mf * 16 + g + half * 8;
                float2 rv = *(const float2*)&resid[(size_t)m * CH + col];
                float2 v = make_float2(acc[mf][nf][half*2]   * CINV + bv.x + rv.x,
                                       acc[mf][nf][half*2+1] * CINV + bv.y + rv.y);
                *(float2*)&outp[(size_t)m * CH + col] = v;
            }
        }
}

// ---------------------------------------------------------------------------
// 3) Flash attention: Q A-frags + K B-frags direct from gmem; V via smem
//    ldmatrix.trans; P in registers. Pure fp16 mma.
// ---------------------------------------------------------------------------
#define APAD 72

__global__ void f16attn() {
    __shared__ __half Vh[64][APAD];

    int tid = threadIdx.x;
    int w = tid >> 5, L = tid & 31;
    int bh = blockIdx.y;
    int q0 = blockIdx.x * 64;

    int a_row_off = ((L >> 3) & 1) * 8 + (L & 7);
    int a_col_off = ((L >> 4) & 1) * 8;
    int g = L >> 2, t2 = (L & 3) * 2;

    // Q fragments direct
    uint4 qfu[4];
    {
        size_t base = ((size_t)bh * (SEQ/16) + (q0 >> 4) + w) * 4;
        #pragma unroll
        for (int ks = 0; ks < 4; ks++)
            qfu[ks] = g_qp[(base + ks) * 32 + L];
    }

    float m0r = -1e30f, m1r = -1e30f, l0 = 0.f, l1 = 0.f;
    float oacc[8][4];
    #pragma unroll
    for (int j = 0; j < 8; j++)
        #pragma unroll
        for (int c = 0; c < 4; c++) oacc[j][c] = 0.f;

    size_t vbase = (size_t)bh * SEQ * HD;
    size_t kbase = (size_t)bh * (SEQ/8);

    for (int s0 = 0; s0 < SEQ; s0 += 64) {
        __syncthreads();   // previous V fully consumed
        #pragma unroll
        for (int i = 0; i < 8; i++) {
            int s = tid + i * 128;
            int kv = s >> 4, d4 = (s & 15) * 4;
            size_t off = vbase + (size_t)(s0 + kv) * HD + d4;
            *(uint2*)&Vh[kv][d4] = *(const uint2*)&g_vh[off];
        }
        __syncthreads();

        // S = Q K^T from direct K B-frags; rescale by 0.125/64 after
        float sacc[8][4];
        #pragma unroll
        for (int j = 0; j < 8; j++)
            #pragma unroll
            for (int c = 0; c < 4; c++) sacc[j][c] = 0.f;
        #pragma unroll
        for (int j = 0; j < 8; j++) {
            size_t tb = (kbase + (s0 >> 3) + j) * 4;
            #pragma unroll
            for (int ks = 0; ks < 4; ks++) {
                uint2 kf = g_kp[(tb + ks) * 32 + L];
                const uint32_t b2[2] = {kf.x, kf.y};
                mma_f16(sacc[j], (const uint32_t*)&qfu[ks], b2);
            }
        }
        #pragma unroll
        for (int j = 0; j < 8; j++)
            #pragma unroll
            for (int c = 0; c < 4; c++) sacc[j][c] *= SMUL;

        // Online softmax on fragments (rows g and g+8 of this warp's 16)
        float mx0 = -1e30f, mx1 = -1e30f;
        #pragma unroll
        for (int j = 0; j < 8; j++) {
            mx0 = fmaxf(mx0, fmaxf(sacc[j][0], sacc[j][1]));
            mx1 = fmaxf(mx1, fmaxf(sacc[j][2], sacc[j][3]));
        }
        #pragma unroll
        for (int o = 1; o <= 2; o <<= 1) {
            mx0 = fmaxf(mx0, __shfl_xor_sync(0xffffffffu, mx0, o));
            mx1 = fmaxf(mx1, __shfl_xor_sync(0xffffffffu, mx1, o));
        }
        float mn0 = fmaxf(m0r, mx0), mn1 = fmaxf(m1r, mx1);
        float f0 = __expf(m0r - mn0), f1 = __expf(m1r - mn1);
        m0r = mn0; m1r = mn1;
        float rs0 = 0.f, rs1 = 0.f;
        #pragma unroll
        for (int j = 0; j < 8; j++) {
            sacc[j][0] = __expf(sacc[j][0] - mn0);
            sacc[j][1] = __expf(sacc[j][1] - mn0);
            sacc[j][2] = __expf(sacc[j][2] - mn1);
            sacc[j][3] = __expf(sacc[j][3] - mn1);
            rs0 += sacc[j][0] + sacc[j][1];
            rs1 += sacc[j][2] + sacc[j][3];
        }
        #pragma unroll
        for (int o = 1; o <= 2; o <<= 1) {
            rs0 += __shfl_xor_sync(0xffffffffu, rs0, o);
            rs1 += __shfl_xor_sync(0xffffffffu, rs1, o);
        }
        l0 = l0 * f0 + rs0;
        l1 = l1 * f1 + rs1;
        #pragma unroll
        for (int j = 0; j < 8; j++) {
            oacc[j][0] *= f0; oacc[j][1] *= f0;
            oacc[j][2] *= f1; oacc[j][3] *= f1;
        }

        // P A-frags in registers (x64, hi only)
        uint32_t pfh[4][4];
        #pragma unroll
        for (int ks = 0; ks < 4; ks++) {
            int j0 = 2 * ks, j1 = 2 * ks + 1;
            pfh[ks][0] = pack_h2(sacc[j0][0] * 64.0f, sacc[j0][1] * 64.0f);
            pfh[ks][1] = pack_h2(sacc[j0][2] * 64.0f, sacc[j0][3] * 64.0f);
            pfh[ks][2] = pack_h2(sacc[j1][0] * 64.0f, sacc[j1][1] * 64.0f);
            pfh[ks][3] = pack_h2(sacc[j1][2] * 64.0f, sacc[j1][3] * 64.0f);
        }

        // O += P V (V via ldmatrix.trans)
        #pragma unroll
        for (int ks = 0; ks < 4; ks++) {
            #pragma unroll
            for (int p = 0; p < 4; p++) {
                uint32_t th[4];
                ldsm4t(th, &Vh[ks * 16 + a_row_off][p * 16 + a_col_off]);
                #pragma unroll
                for (int q = 0; q < 2; q++) {
                    int j = 2 * p + q;
                    const uint32_t bh2[2] = {th[2*q], th[2*q+1]};
                    mma_f16(oacc[j], pfh[ks], bh2);
                }
            }
        }
    }

    // Epilogue: write att as A-frags (x8 rep = oacc/(64 l))
    int b = bh / NH, h = bh % NH;
    float inv0 = QK64 / l0, inv1 = QK64 / l1;
    size_t tmt = (size_t)b * (SEQ/16) + (q0 >> 4) + w;
    #pragma unroll
    for (int u = 0; u < 4; u++) {
        int ck = h * 4 + u;
        uint4 v;
        v.x = pack_h2(oacc[2*u  ][0] * inv0, oacc[2*u  ][1] * inv0);
        v.y = pack_h2(oacc[2*u  ][2] * inv1, oacc[2*u  ][3] * inv1);
        v.z = pack_h2(oacc[2*u+1][0] * inv0, oacc[2*u+1][1] * inv0);
        v.w = pack_h2(oacc[2*u+1][2] * inv1, oacc[2*u+1][3] * inv1);
        g_attp[(tmt * (CH/16) + ck) * 32 + L] = v;
    }
}

// ---------------------------------------------------------------------------
extern "C" void kernel_launch(void* const* d_in, const int* in_sizes, int n_in,
                              void* d_out, int out_size) {
    const float* img   = (const float*)d_in[0];
    const float* gamma = (const float*)d_in[1];
    const float* beta  = (const float*)d_in[2];
    const float* w_qkv = (const float*)d_in[3];
    const float* w_out = (const float*)d_in[4];
    const float* b_out = (const float*)d_in[5];
    float* out = (float*)d_out;

    uint2 *wqh, *wql, *woh, *wol;
    cudaGetSymbolAddress((void**)&wqh, g_wqph);
    cudaGetSymbolAddress((void**)&wql, g_wqpl);
    cudaGetSymbolAddress((void**)&woh, g_woph);
    cudaGetSymbolAddress((void**)&wol, g_wopl);

    int wq_total = (CH/16)*(C3/8)*32;
    int wo_total = (CH/16)*(CH/8)*32;
    wpack_kernel<<<(wq_total + 255) / 256, 256>>>(w_qkv, wqh, wql, C3, wq_total);
    wpack_kernel<<<(wo_total + 255) / 256, 256>>>(w_out, woh, wol, CH, wo_total);
    ln_kernel<<<TOK, 384>>>(img, gamma, beta);
    f16gemm_qkv<<<dim3(C3 / GBN, TOK / GBM), 128>>>();
    f16attn<<<dim3(SEQ / 64, BH), 128>>>();
    f16gemm_out<<<dim3(CH / GBN, TOK / GBM), 128>>>(b_out, img, out);
}